// round 6
// baseline (speedup 1.0000x reference)
#include <cuda_runtime.h>

typedef unsigned long long ull;

static constexpr int T  = 256;
static constexpr int F  = 16;
static constexpr int U1 = 24;
static constexpr int U2 = 48;
#define LN_EPS 1e-3f

// ---------------- packed f32x2 helpers ----------------
__device__ __forceinline__ ull pk2(float lo, float hi) {
    ull r; asm("mov.b64 %0, {%1, %2};" : "=l"(r) : "f"(lo), "f"(hi)); return r;
}
__device__ __forceinline__ ull dup2(float v) { return pk2(v, v); }
__device__ __forceinline__ float2 un2(ull p) {
    float2 r; asm("mov.b64 {%0, %1}, %2;" : "=f"(r.x), "=f"(r.y) : "l"(p)); return r;
}
__device__ __forceinline__ ull ffma2(ull a, ull b, ull c) {
    ull d; asm("fma.rn.f32x2 %0, %1, %2, %3;" : "=l"(d) : "l"(a), "l"(b), "l"(c)); return d;
}
__device__ __forceinline__ ull fadd2(ull a, ull b) {
    ull d; asm("add.rn.f32x2 %0, %1, %2;" : "=l"(d) : "l"(a), "l"(b)); return d;
}
__device__ __forceinline__ ull fmul2(ull a, ull b) {
    ull d; asm("mul.rn.f32x2 %0, %1, %2;" : "=l"(d) : "l"(a), "l"(b)); return d;
}

// branch-free accurate tanh: 1 - 2/(1+e^{2x})
__device__ __forceinline__ float tanh_f(float x) {
    float e = __expf(2.0f * x);
    return 1.0f - __fdividef(2.0f, 1.0f + e);
}

__device__ __forceinline__ ull mkp(float lo, float hi) {
    return ((ull)__float_as_uint(hi) << 32) | __float_as_uint(lo);
}

// ---------------- packed weight bundle ----------------
// Parity p (= lane&3) owns: u1 pairs 3p..3p+2 (units 6p..6p+5),
//                           u2 pairs 6p..6p+5 (units 12p..12p+11).
// k-pair-merged: W1q[kp][p][j]: j0..2 = k=2kp pairs, j3..5 = k=2kp+1.
// W2q/Wr2q: j0..5 = k=2kp, j6..11 = k=2kp+1.
struct __align__(16) CWq {
    ull W1q [8][4][6];
    ull Wr1q[12][4][6];
    ull W2q [12][4][12];   // g1-folded
    ull Wr2q[24][4][12];
    ull Bs  [4][24];       // [0..2]=b1, [3..5]=br1, [6..11]=b2f, [12..17]=Cc, [18..23]=br2
    ull G2f [24];
    ull Be2f[24];
    ull Wof [24];
    float bout;
    float pad[3];
};
__device__ CWq d_stage;

// ---------------- prep kernel ----------------
__global__ void prep_kernel(const float* __restrict__ W1,  const float* __restrict__ b1,
                            const float* __restrict__ Wr1, const float* __restrict__ br1,
                            const float* __restrict__ g1,  const float* __restrict__ be1,
                            const float* __restrict__ W2,  const float* __restrict__ b2,
                            const float* __restrict__ Wr2, const float* __restrict__ br2,
                            const float* __restrict__ g2,  const float* __restrict__ be2,
                            const float* __restrict__ Wout, const float* __restrict__ bout)
{
    const int tid = threadIdx.x;  // 256 threads

    for (int idx = tid; idx < 8 * 4 * 6; idx += 256) {
        int kp = idx / 24, p = (idx / 6) % 4, j = idx % 6;
        int k = 2 * kp + j / 3, u = 6 * p + 2 * (j % 3);
        d_stage.W1q[kp][p][j] = mkp(W1[k * U1 + u], W1[k * U1 + u + 1]);
    }
    for (int idx = tid; idx < 12 * 4 * 6; idx += 256) {
        int kp = idx / 24, p = (idx / 6) % 4, j = idx % 6;
        int k = 2 * kp + j / 3, u = 6 * p + 2 * (j % 3);
        d_stage.Wr1q[kp][p][j] = mkp(Wr1[k * U1 + u], Wr1[k * U1 + u + 1]);
    }
    for (int idx = tid; idx < 12 * 4 * 12; idx += 256) {
        int kp = idx / 48, p = (idx / 12) % 4, j = idx % 12;
        int k = 2 * kp + j / 6, u = 12 * p + 2 * (j % 6);
        d_stage.W2q[kp][p][j] = mkp(g1[k] * W2[k * U2 + u], g1[k] * W2[k * U2 + u + 1]);
    }
    for (int idx = tid; idx < 24 * 4 * 12; idx += 256) {
        int kp = idx / 48, p = (idx / 12) % 4, j = idx % 12;
        int k = 2 * kp + j / 6, u = 12 * p + 2 * (j % 6);
        d_stage.Wr2q[kp][p][j] = mkp(Wr2[k * U2 + u], Wr2[k * U2 + u + 1]);
    }
    for (int idx = tid; idx < 4 * 24; idx += 256) {
        int p = idx / 24, j = idx % 24;
        ull v;
        if (j < 3) {                 // b1
            int u = 6 * p + 2 * j;
            v = mkp(b1[u], b1[u + 1]);
        } else if (j < 6) {          // br1
            int u = 6 * p + 2 * (j - 3);
            v = mkp(br1[u], br1[u + 1]);
        } else if (j < 12) {         // b2f = b2 + be1 @ W2
            int u = 12 * p + 2 * (j - 6);
            float lo = b2[u], hi = b2[u + 1];
            for (int k = 0; k < U1; ++k) {
                lo += be1[k] * W2[k * U2 + u];
                hi += be1[k] * W2[k * U2 + u + 1];
            }
            v = mkp(lo, hi);
        } else if (j < 18) {         // Cc = column sums of g1-folded W2
            int u = 12 * p + 2 * (j - 12);
            float lo = 0.f, hi = 0.f;
            for (int k = 0; k < U1; ++k) {
                lo += g1[k] * W2[k * U2 + u];
                hi += g1[k] * W2[k * U2 + u + 1];
            }
            v = mkp(lo, hi);
        } else {                     // br2
            int u = 12 * p + 2 * (j - 18);
            v = mkp(br2[u], br2[u + 1]);
        }
        d_stage.Bs[p][j] = v;
    }
    for (int idx = tid; idx < 24; idx += 256) {
        int u = 2 * idx;
        d_stage.G2f[idx]  = mkp(g2[u],   g2[u + 1]);
        d_stage.Be2f[idx] = mkp(be2[u],  be2[u + 1]);
        d_stage.Wof[idx]  = mkp(Wout[u], Wout[u + 1]);
    }
    if (tid == 0) d_stage.bout = bout[0];
}

// ---------------- smem: shared weights + per-warp private buffers ----------------
struct __align__(16) WarpBuf {
    ull sx[12][16];           // x pairs    [pair][row]
    ull sn[12][16];           // ns1 pairs
    ull sy[24][16];           // y / final ns2 pairs
    float2 sinb[2][8][16];    // staged input [buf][featpair][row]
};
struct __align__(16) Smem {
    CWq cw;
    WarpBuf wb[4];
};

// ---------------- main scan kernel ----------------
// 128 threads = 4 INDEPENDENT warps x 16 rows. lane = (g = row-quad, p = unit parity).
// Lane handles rows 2g,2g+1 and 1/4 of the units. No __syncthreads in the loop.
__global__ __launch_bounds__(128, 1)
void rnn_main(const float* __restrict__ seq, float* __restrict__ out)
{
    extern __shared__ __align__(16) char smem_raw[];
    Smem* S = reinterpret_cast<Smem*>(smem_raw);

    const int tid  = threadIdx.x;
    const int w    = tid >> 5;
    const int lane = tid & 31;
    const int g    = lane >> 2;
    const int p    = lane & 3;
    const int r0   = 2 * g;

    // cooperative weight copy (whole CTA), then one CTA barrier
    {
        const ull* gsrc = reinterpret_cast<const ull*>(&d_stage);
        ull* sdst = reinterpret_cast<ull*>(&S->cw);
        const int N = (int)(sizeof(CWq) / 8);
        for (int i = tid; i < N; i += 128) sdst[i] = gsrc[i];
    }
    __syncthreads();

    WarpBuf* Wb = &S->wb[w];
    const int wrow = blockIdx.x * 64 + w * 16;

    // staging role: lane covers (srow = lane>>1, half = lane&1): 8 floats/step
    const int srow = lane >> 1, half = lane & 1;
    const float4* gp = reinterpret_cast<const float4*>(
                           seq + (size_t)(wrow + srow) * (T * F) + half * 8);

    // stage t=0
    {
        float4 v0 = gp[0], v1 = gp[1];
        Wb->sinb[0][4 * half + 0][srow] = make_float2(v0.x, v0.y);
        Wb->sinb[0][4 * half + 1][srow] = make_float2(v0.z, v0.w);
        Wb->sinb[0][4 * half + 2][srow] = make_float2(v1.x, v1.y);
        Wb->sinb[0][4 * half + 3][srow] = make_float2(v1.z, v1.w);
    }
    __syncwarp();

    ull s1[2][3] = {{0,0,0},{0,0,0}};
    ull s2[2][6] = {{0,0,0,0,0,0},{0,0,0,0,0,0}};

    for (int t = 0; t < T; ++t) {
        const int cur = t & 1, nxt = cur ^ 1;
        const int tn = (t < T - 1) ? (t + 1) : t;
        float4 nv0 = gp[tn * 4], nv1 = gp[tn * 4 + 1];

        // ---- Phase A: x = in@W1 + b1 + s1 (own 3 pairs, 2 rows) ----
        ull a[2][3];
        #pragma unroll
        for (int j = 0; j < 3; ++j) {
            ull bb = S->cw.Bs[p][j];
            a[0][j] = fadd2(s1[0][j], bb);
            a[1][j] = fadd2(s1[1][j], bb);
        }
        #pragma unroll
        for (int kp = 0; kp < 8; ++kp) {
            const ulonglong2* q = reinterpret_cast<const ulonglong2*>(S->cw.W1q[kp][p]);
            ulonglong2 q0 = q[0], q1 = q[1], q2 = q[2];
            #pragma unroll
            for (int rr = 0; rr < 2; ++rr) {
                float2 f = Wb->sinb[cur][kp][r0 + rr];
                ull k0 = dup2(f.x), k1 = dup2(f.y);
                a[rr][0] = ffma2(k0, q0.x, a[rr][0]);
                a[rr][1] = ffma2(k0, q0.y, a[rr][1]);
                a[rr][2] = ffma2(k0, q1.x, a[rr][2]);
                a[rr][0] = ffma2(k1, q1.y, a[rr][0]);
                a[rr][1] = ffma2(k1, q2.x, a[rr][1]);
                a[rr][2] = ffma2(k1, q2.y, a[rr][2]);
            }
        }
        #pragma unroll
        for (int j = 0; j < 3; ++j)
            *reinterpret_cast<ulonglong2*>(&Wb->sx[3 * p + j][r0]) =
                make_ulonglong2(a[0][j], a[1][j]);
        __syncwarp();

        // ---- Phase B: ns1 = tanh(x@Wr1 + br1) ----
        ull b[2][3];
        #pragma unroll
        for (int j = 0; j < 3; ++j) {
            ull bb = S->cw.Bs[p][3 + j];
            b[0][j] = bb; b[1][j] = bb;
        }
        #pragma unroll
        for (int pp = 0; pp < 12; ++pp) {
            const ulonglong2* q = reinterpret_cast<const ulonglong2*>(S->cw.Wr1q[pp][p]);
            ulonglong2 q0 = q[0], q1 = q[1], q2 = q[2];
            ulonglong2 X = *reinterpret_cast<const ulonglong2*>(&Wb->sx[pp][r0]);
            #pragma unroll
            for (int rr = 0; rr < 2; ++rr) {
                float2 u = un2(rr == 0 ? X.x : X.y);
                ull k0 = dup2(u.x), k1 = dup2(u.y);
                b[rr][0] = ffma2(k0, q0.x, b[rr][0]);
                b[rr][1] = ffma2(k0, q0.y, b[rr][1]);
                b[rr][2] = ffma2(k0, q1.x, b[rr][2]);
                b[rr][0] = ffma2(k1, q1.y, b[rr][0]);
                b[rr][1] = ffma2(k1, q2.x, b[rr][1]);
                b[rr][2] = ffma2(k1, q2.y, b[rr][2]);
            }
        }
        #pragma unroll
        for (int rr = 0; rr < 2; ++rr) {
            float2 u;
            u = un2(b[rr][0]); s1[rr][0] = pk2(tanh_f(u.x), tanh_f(u.y));
            u = un2(b[rr][1]); s1[rr][1] = pk2(tanh_f(u.x), tanh_f(u.y));
            u = un2(b[rr][2]); s1[rr][2] = pk2(tanh_f(u.x), tanh_f(u.y));
        }
        #pragma unroll
        for (int j = 0; j < 3; ++j)
            *reinterpret_cast<ulonglong2*>(&Wb->sn[3 * p + j][r0]) =
                make_ulonglong2(s1[0][j], s1[1][j]);
        __syncwarp();

        // ---- Phase C: y = LN1-folded(ns1)@W2 + b2f + s2 ----
        ull c[2][6] = {{0,0,0,0,0,0},{0,0,0,0,0,0}};
        ull sm2[2] = {0,0}, sq2[2] = {0,0};
        #pragma unroll
        for (int pp = 0; pp < 12; ++pp) {
            const ulonglong2* q = reinterpret_cast<const ulonglong2*>(S->cw.W2q[pp][p]);
            ulonglong2 q0 = q[0], q1 = q[1], q2 = q[2];
            ulonglong2 q3 = q[3], q4 = q[4], q5 = q[5];
            ulonglong2 X = *reinterpret_cast<const ulonglong2*>(&Wb->sn[pp][r0]);
            sm2[0] = fadd2(sm2[0], X.x); sq2[0] = ffma2(X.x, X.x, sq2[0]);
            sm2[1] = fadd2(sm2[1], X.y); sq2[1] = ffma2(X.y, X.y, sq2[1]);
            #pragma unroll
            for (int rr = 0; rr < 2; ++rr) {
                float2 u = un2(rr == 0 ? X.x : X.y);
                ull k0 = dup2(u.x), k1 = dup2(u.y);
                c[rr][0] = ffma2(k0, q0.x, c[rr][0]);
                c[rr][1] = ffma2(k0, q0.y, c[rr][1]);
                c[rr][2] = ffma2(k0, q1.x, c[rr][2]);
                c[rr][3] = ffma2(k0, q1.y, c[rr][3]);
                c[rr][4] = ffma2(k0, q2.x, c[rr][4]);
                c[rr][5] = ffma2(k0, q2.y, c[rr][5]);
                c[rr][0] = ffma2(k1, q3.x, c[rr][0]);
                c[rr][1] = ffma2(k1, q3.y, c[rr][1]);
                c[rr][2] = ffma2(k1, q4.x, c[rr][2]);
                c[rr][3] = ffma2(k1, q4.y, c[rr][3]);
                c[rr][4] = ffma2(k1, q5.x, c[rr][4]);
                c[rr][5] = ffma2(k1, q5.y, c[rr][5]);
            }
        }
        #pragma unroll
        for (int rr = 0; rr < 2; ++rr) {
            float2 us = un2(sm2[rr]), uq = un2(sq2[rr]);
            float mu   = (us.x + us.y) * (1.0f / 24.0f);
            float var  = fmaf(-mu, mu, (uq.x + uq.y) * (1.0f / 24.0f));
            float rstd = rsqrtf(var + LN_EPS);
            ull mun = dup2(-mu), rsd = dup2(rstd);
            #pragma unroll
            for (int j = 0; j < 6; ++j)
                c[rr][j] = ffma2(rsd, ffma2(mun, S->cw.Bs[p][12 + j], c[rr][j]),
                                 fadd2(S->cw.Bs[p][6 + j], s2[rr][j]));
        }
        #pragma unroll
        for (int j = 0; j < 6; ++j)
            *reinterpret_cast<ulonglong2*>(&Wb->sy[6 * p + j][r0]) =
                make_ulonglong2(c[0][j], c[1][j]);
        // stage next input
        Wb->sinb[nxt][4 * half + 0][srow] = make_float2(nv0.x, nv0.y);
        Wb->sinb[nxt][4 * half + 1][srow] = make_float2(nv0.z, nv0.w);
        Wb->sinb[nxt][4 * half + 2][srow] = make_float2(nv1.x, nv1.y);
        Wb->sinb[nxt][4 * half + 3][srow] = make_float2(nv1.z, nv1.w);
        __syncwarp();

        // ---- Phase D: ns2 = tanh(y@Wr2 + br2) ----
        ull d[2][6];
        #pragma unroll
        for (int j = 0; j < 6; ++j) {
            ull bb = S->cw.Bs[p][18 + j];
            d[0][j] = bb; d[1][j] = bb;
        }
        #pragma unroll
        for (int pp = 0; pp < 24; ++pp) {
            const ulonglong2* q = reinterpret_cast<const ulonglong2*>(S->cw.Wr2q[pp][p]);
            ulonglong2 q0 = q[0], q1 = q[1], q2 = q[2];
            ulonglong2 q3 = q[3], q4 = q[4], q5 = q[5];
            ulonglong2 X = *reinterpret_cast<const ulonglong2*>(&Wb->sy[pp][r0]);
            #pragma unroll
            for (int rr = 0; rr < 2; ++rr) {
                float2 u = un2(rr == 0 ? X.x : X.y);
                ull k0 = dup2(u.x), k1 = dup2(u.y);
                d[rr][0] = ffma2(k0, q0.x, d[rr][0]);
                d[rr][1] = ffma2(k0, q0.y, d[rr][1]);
                d[rr][2] = ffma2(k0, q1.x, d[rr][2]);
                d[rr][3] = ffma2(k0, q1.y, d[rr][3]);
                d[rr][4] = ffma2(k0, q2.x, d[rr][4]);
                d[rr][5] = ffma2(k0, q2.y, d[rr][5]);
                d[rr][0] = ffma2(k1, q3.x, d[rr][0]);
                d[rr][1] = ffma2(k1, q3.y, d[rr][1]);
                d[rr][2] = ffma2(k1, q4.x, d[rr][2]);
                d[rr][3] = ffma2(k1, q4.y, d[rr][3]);
                d[rr][4] = ffma2(k1, q5.x, d[rr][4]);
                d[rr][5] = ffma2(k1, q5.y, d[rr][5]);
            }
        }
        #pragma unroll
        for (int rr = 0; rr < 2; ++rr) {
            #pragma unroll
            for (int j = 0; j < 6; ++j) {
                float2 u = un2(d[rr][j]);
                s2[rr][j] = pk2(tanh_f(u.x), tanh_f(u.y));
            }
        }
        // next iteration's Phase A writes sx (last read pre-snsync); sy rewrite
        // in next Phase C is gated by next snsync. No barrier needed here.
    }

    // ---- epilogue: sigmoid(LN(s2; g2,be2) @ Wout + bout) ----
    __syncwarp();
    #pragma unroll
    for (int j = 0; j < 6; ++j)
        *reinterpret_cast<ulonglong2*>(&Wb->sy[6 * p + j][r0]) =
            make_ulonglong2(s2[0][j], s2[1][j]);
    __syncwarp();

    if ((lane & 1) == 0) {
        const int row = lane >> 1;       // 0..15
        ull zp[24];
        #pragma unroll
        for (int pp = 0; pp < 24; ++pp) zp[pp] = Wb->sy[pp][row];
        ull sm2 = zp[0], sq2 = fmul2(zp[0], zp[0]);
        #pragma unroll
        for (int pp = 1; pp < 24; ++pp) {
            sm2 = fadd2(sm2, zp[pp]);
            sq2 = ffma2(zp[pp], zp[pp], sq2);
        }
        float2 us = un2(sm2), uq = un2(sq2);
        float mu   = (us.x + us.y) * (1.0f / 48.0f);
        float var  = fmaf(-mu, mu, (uq.x + uq.y) * (1.0f / 48.0f));
        float rstd = rsqrtf(var + LN_EPS);
        ull mun = dup2(-mu), rsd = dup2(rstd);
        ull acc = 0;
        #pragma unroll
        for (int pp = 0; pp < 24; ++pp) {
            ull h = fmul2(fadd2(zp[pp], mun), rsd);
            h = ffma2(h, S->cw.G2f[pp], S->cw.Be2f[pp]);
            acc = ffma2(h, S->cw.Wof[pp], acc);
        }
        float2 ua = un2(acc);
        float z = ua.x + ua.y + S->cw.bout;
        out[wrow + row] = __fdividef(1.0f, 1.0f + __expf(-z));
    }
}

extern "C" void kernel_launch(void* const* d_in, const int* in_sizes, int n_in,
                              void* d_out, int out_size)
{
    const float* seq  = (const float*)d_in[0];
    const float* W1   = (const float*)d_in[1];
    const float* b1   = (const float*)d_in[2];
    const float* Wr1  = (const float*)d_in[3];
    const float* br1  = (const float*)d_in[4];
    const float* g1   = (const float*)d_in[5];
    const float* be1  = (const float*)d_in[6];
    const float* W2   = (const float*)d_in[7];
    const float* b2   = (const float*)d_in[8];
    const float* Wr2  = (const float*)d_in[9];
    const float* br2  = (const float*)d_in[10];
    const float* g2   = (const float*)d_in[11];
    const float* be2  = (const float*)d_in[12];
    const float* Wout = (const float*)d_in[13];
    const float* bout = (const float*)d_in[14];

    prep_kernel<<<1, 256>>>(W1, b1, Wr1, br1, g1, be1,
                            W2, b2, Wr2, br2, g2, be2, Wout, bout);

    static int smem_configured = 0;
    if (!smem_configured) {
        cudaFuncSetAttribute(rnn_main, cudaFuncAttributeMaxDynamicSharedMemorySize,
                             (int)sizeof(Smem));
        smem_configured = 1;
    }

    const int B = in_sizes[0] / (T * F);     // 8192
    rnn_main<<<B / 64, 128, sizeof(Smem)>>>(seq, (float*)d_out);
}

// round 7
// speedup vs baseline: 1.1270x; 1.1270x over previous
#include <cuda_runtime.h>

typedef unsigned long long ull;

static constexpr int T  = 256;
static constexpr int F  = 16;
static constexpr int U1 = 24;
static constexpr int U2 = 48;
#define LN_EPS 1e-3f

// ---------------- packed f32x2 helpers ----------------
__device__ __forceinline__ ull pk2(float lo, float hi) {
    ull r; asm("mov.b64 %0, {%1, %2};" : "=l"(r) : "f"(lo), "f"(hi)); return r;
}
__device__ __forceinline__ ull dup2(float v) { return pk2(v, v); }
__device__ __forceinline__ float2 un2(ull p) {
    float2 r; asm("mov.b64 {%0, %1}, %2;" : "=f"(r.x), "=f"(r.y) : "l"(p)); return r;
}
__device__ __forceinline__ ull ffma2(ull a, ull b, ull c) {
    ull d; asm("fma.rn.f32x2 %0, %1, %2, %3;" : "=l"(d) : "l"(a), "l"(b), "l"(c)); return d;
}
__device__ __forceinline__ ull fadd2(ull a, ull b) {
    ull d; asm("add.rn.f32x2 %0, %1, %2;" : "=l"(d) : "l"(a), "l"(b)); return d;
}
__device__ __forceinline__ ull fmul2(ull a, ull b) {
    ull d; asm("mul.rn.f32x2 %0, %1, %2;" : "=l"(d) : "l"(a), "l"(b)); return d;
}

// branch-free accurate tanh: 1 - 2/(1+e^{2x})
__device__ __forceinline__ float tanh_f(float x) {
    float e = __expf(2.0f * x);
    return 1.0f - __fdividef(2.0f, 1.0f + e);
}

__device__ __forceinline__ ull mkp(float lo, float hi) {
    return ((ull)__float_as_uint(hi) << 32) | __float_as_uint(lo);
}

// ---------------- packed weight bundle ----------------
// Layer1: per-slice w (4 slices of 3 u1-pairs). Layer2: per-warp q (8 slices of 3 u2-pairs).
// k-pair-merged rows: [..][p][6]: j0..2 = k=2p (3 pairs), j3..5 = k=2p+1.
struct __align__(16) CW8 {
    ull W1m [4][8][6];     // layer1 input
    ull Wr1m[4][12][6];    // layer1 recurrent
    ull W2o [8][12][6];    // layer2 input, g1-folded
    ull Wr2o[8][24][6];    // layer2 recurrent
    ull Bs1 [4][6];        // [0..2]=b1 pairs, [3..5]=br1 pairs (slice w)
    ull Bs2 [8][9];        // [0..2]=b2f, [3..5]=Cc, [6..8]=br2 (slice q)
    ull G2f [24];
    ull Be2f[24];
    ull Wof [24];
    float bout;
    float pad[3];
};
__device__ CW8 d_stage;

// ---------------- prep kernel ----------------
__global__ void prep_kernel(const float* __restrict__ W1,  const float* __restrict__ b1,
                            const float* __restrict__ Wr1, const float* __restrict__ br1,
                            const float* __restrict__ g1,  const float* __restrict__ be1,
                            const float* __restrict__ W2,  const float* __restrict__ b2,
                            const float* __restrict__ Wr2, const float* __restrict__ br2,
                            const float* __restrict__ g2,  const float* __restrict__ be2,
                            const float* __restrict__ Wout, const float* __restrict__ bout)
{
    const int tid = threadIdx.x;  // 256 threads

    for (int idx = tid; idx < 4 * 8 * 6; idx += 256) {
        int w = idx / 48, kp = (idx / 6) % 8, j = idx % 6;
        int k = 2 * kp + j / 3, u = 6 * w + 2 * (j % 3);
        d_stage.W1m[w][kp][j] = mkp(W1[k * U1 + u], W1[k * U1 + u + 1]);
    }
    for (int idx = tid; idx < 4 * 12 * 6; idx += 256) {
        int w = idx / 72, p = (idx / 6) % 12, j = idx % 6;
        int k = 2 * p + j / 3, u = 6 * w + 2 * (j % 3);
        d_stage.Wr1m[w][p][j] = mkp(Wr1[k * U1 + u], Wr1[k * U1 + u + 1]);
    }
    for (int idx = tid; idx < 8 * 12 * 6; idx += 256) {
        int q = idx / 72, p = (idx / 6) % 12, j = idx % 6;
        int k = 2 * p + j / 3, u = 6 * q + 2 * (j % 3);
        d_stage.W2o[q][p][j] = mkp(g1[k] * W2[k * U2 + u], g1[k] * W2[k * U2 + u + 1]);
    }
    for (int idx = tid; idx < 8 * 24 * 6; idx += 256) {
        int q = idx / 144, p = (idx / 6) % 24, j = idx % 6;
        int k = 2 * p + j / 3, u = 6 * q + 2 * (j % 3);
        d_stage.Wr2o[q][p][j] = mkp(Wr2[k * U2 + u], Wr2[k * U2 + u + 1]);
    }
    for (int idx = tid; idx < 4 * 6; idx += 256) {
        int w = idx / 6, j = idx % 6;
        if (j < 3) {
            int u = 6 * w + 2 * j;
            d_stage.Bs1[w][j] = mkp(b1[u], b1[u + 1]);
        } else {
            int u = 6 * w + 2 * (j - 3);
            d_stage.Bs1[w][j] = mkp(br1[u], br1[u + 1]);
        }
    }
    for (int idx = tid; idx < 8 * 9; idx += 256) {
        int q = idx / 9, j = idx % 9;
        ull v;
        if (j < 3) {                 // b2f = b2 + be1 @ W2
            int u = 6 * q + 2 * j;
            float lo = b2[u], hi = b2[u + 1];
            for (int k = 0; k < U1; ++k) {
                lo += be1[k] * W2[k * U2 + u];
                hi += be1[k] * W2[k * U2 + u + 1];
            }
            v = mkp(lo, hi);
        } else if (j < 6) {          // Cc = column sums of g1-folded W2
            int u = 6 * q + 2 * (j - 3);
            float lo = 0.f, hi = 0.f;
            for (int k = 0; k < U1; ++k) {
                lo += g1[k] * W2[k * U2 + u];
                hi += g1[k] * W2[k * U2 + u + 1];
            }
            v = mkp(lo, hi);
        } else {                     // br2
            int u = 6 * q + 2 * (j - 6);
            v = mkp(br2[u], br2[u + 1]);
        }
        d_stage.Bs2[q][j] = v;
    }
    for (int idx = tid; idx < 24; idx += 256) {
        int u = 2 * idx;
        d_stage.G2f[idx]  = mkp(g2[u],   g2[u + 1]);
        d_stage.Be2f[idx] = mkp(be2[u],  be2[u + 1]);
        d_stage.Wof[idx]  = mkp(Wout[u], Wout[u + 1]);
    }
    if (tid == 0) d_stage.bout = bout[0];
}

// ---------------- smem layout ----------------
struct __align__(16) Smem8 {
    CW8 cw;
    ull sx[12][64];           // x pairs    [pair][row]
    ull sn[12][64];           // ns1 pairs
    ull sy[24][64];           // y pairs / final ns2 pairs
    float2 sinb[2][8][64];    // staged input [buf][featpair][row]
};

// ---------------- main scan kernel ----------------
// 256 threads = 8 warps, 64 rows/CTA, grid 128.
// Layer1: warp (w = q>>1, h = q&1): unit-slice w, row-half h, 1 row/lane.
// Layer2: warp q: u2 pairs 3q..3q+2, all 64 rows, 2 rows/lane.
__global__ __launch_bounds__(256, 1)
void rnn_main(const float* __restrict__ seq, float* __restrict__ out)
{
    extern __shared__ __align__(16) char smem_raw[];
    Smem8* S = reinterpret_cast<Smem8*>(smem_raw);

    const int tid  = threadIdx.x;
    const int q    = tid >> 5;
    const int lane = tid & 31;
    const int w    = q >> 1;          // layer1 unit-slice
    const int h    = q & 1;           // layer1 row-half
    const int row1 = 32 * h + lane;   // layer1 row
    const int r0   = 2 * lane;        // layer2 first row
    const int rowbase = blockIdx.x * 64;

    // cooperative weight copy
    {
        const ull* gsrc = reinterpret_cast<const ull*>(&d_stage);
        ull* sdst = reinterpret_cast<ull*>(&S->cw);
        const int N = (int)(sizeof(CW8) / 8);
        for (int i = tid; i < N; i += 256) sdst[i] = gsrc[i];
    }

    // input staging: thread covers (srow = tid&63, quarter = tid>>6) -> 1 float4/step
    const int srow = tid & 63, qa = tid >> 6;
    const float4* gp = reinterpret_cast<const float4*>(
                           seq + (size_t)(rowbase + srow) * (T * F)) + qa;
    {
        float4 v = gp[0];
        S->sinb[0][2 * qa + 0][srow] = make_float2(v.x, v.y);
        S->sinb[0][2 * qa + 1][srow] = make_float2(v.z, v.w);
    }
    __syncthreads();

    ull s1[3] = {0ull, 0ull, 0ull};                     // layer1 state (row1, pairs 3w+j)
    ull s2[2][3] = {{0,0,0},{0,0,0}};                   // layer2 state (rows r0..+1, pairs 3q+j)

    for (int t = 0; t < T; ++t) {
        const int cur = t & 1, nxt = cur ^ 1;
        const int tn = (t < T - 1) ? (t + 1) : t;
        float4 nv = gp[tn * 4];

        // ---- Phase A (layer1): x = in@W1 + b1 + s1, one row ----
        ull a0 = fadd2(s1[0], S->cw.Bs1[w][0]);
        ull a1 = fadd2(s1[1], S->cw.Bs1[w][1]);
        ull a2 = fadd2(s1[2], S->cw.Bs1[w][2]);
        #pragma unroll
        for (int kp = 0; kp < 8; ++kp) {
            const ulonglong2* wq = reinterpret_cast<const ulonglong2*>(S->cw.W1m[w][kp]);
            ulonglong2 q0 = wq[0], q1 = wq[1], q2 = wq[2];
            float2 f = S->sinb[cur][kp][row1];
            ull k0 = dup2(f.x), k1 = dup2(f.y);
            a0 = ffma2(k0, q0.x, a0); a1 = ffma2(k0, q0.y, a1); a2 = ffma2(k0, q1.x, a2);
            a0 = ffma2(k1, q1.y, a0); a1 = ffma2(k1, q2.x, a1); a2 = ffma2(k1, q2.y, a2);
        }
        S->sx[3 * w + 0][row1] = a0;
        S->sx[3 * w + 1][row1] = a1;
        S->sx[3 * w + 2][row1] = a2;
        __syncthreads();

        // ---- Phase B (layer1): ns1 = tanh(x@Wr1 + br1), one row ----
        ull b0 = S->cw.Bs1[w][3], b1v = S->cw.Bs1[w][4], b2v = S->cw.Bs1[w][5];
        #pragma unroll
        for (int pp = 0; pp < 12; ++pp) {
            const ulonglong2* wq = reinterpret_cast<const ulonglong2*>(S->cw.Wr1m[w][pp]);
            ulonglong2 q0 = wq[0], q1 = wq[1], q2 = wq[2];
            float2 u = un2(S->sx[pp][row1]);
            ull k0 = dup2(u.x), k1 = dup2(u.y);
            b0  = ffma2(k0, q0.x, b0); b1v = ffma2(k0, q0.y, b1v); b2v = ffma2(k0, q1.x, b2v);
            b0  = ffma2(k1, q1.y, b0); b1v = ffma2(k1, q2.x, b1v); b2v = ffma2(k1, q2.y, b2v);
        }
        {
            float2 u;
            u = un2(b0);  s1[0] = pk2(tanh_f(u.x), tanh_f(u.y));
            u = un2(b1v); s1[1] = pk2(tanh_f(u.x), tanh_f(u.y));
            u = un2(b2v); s1[2] = pk2(tanh_f(u.x), tanh_f(u.y));
        }
        S->sn[3 * w + 0][row1] = s1[0];
        S->sn[3 * w + 1][row1] = s1[1];
        S->sn[3 * w + 2][row1] = s1[2];
        __syncthreads();

        // ---- Phase C (layer2): y = LN1-folded(ns1)@W2 + b2f + s2, own 3 pairs, 2 rows ----
        ull c[2][3] = {{0,0,0},{0,0,0}};
        ull sm2[2] = {0,0}, sq2[2] = {0,0};
        #pragma unroll
        for (int pp = 0; pp < 12; ++pp) {
            const ulonglong2* wq = reinterpret_cast<const ulonglong2*>(S->cw.W2o[q][pp]);
            ulonglong2 q0 = wq[0], q1 = wq[1], q2 = wq[2];
            ulonglong2 X = *reinterpret_cast<const ulonglong2*>(&S->sn[pp][r0]);
            sm2[0] = fadd2(sm2[0], X.x); sq2[0] = ffma2(X.x, X.x, sq2[0]);
            sm2[1] = fadd2(sm2[1], X.y); sq2[1] = ffma2(X.y, X.y, sq2[1]);
            float2 u0 = un2(X.x), u1 = un2(X.y);
            ull k0 = dup2(u0.x), k1 = dup2(u0.y);
            c[0][0] = ffma2(k0, q0.x, c[0][0]);
            c[0][1] = ffma2(k0, q0.y, c[0][1]);
            c[0][2] = ffma2(k0, q1.x, c[0][2]);
            c[0][0] = ffma2(k1, q1.y, c[0][0]);
            c[0][1] = ffma2(k1, q2.x, c[0][1]);
            c[0][2] = ffma2(k1, q2.y, c[0][2]);
            ull m0 = dup2(u1.x), m1 = dup2(u1.y);
            c[1][0] = ffma2(m0, q0.x, c[1][0]);
            c[1][1] = ffma2(m0, q0.y, c[1][1]);
            c[1][2] = ffma2(m0, q1.x, c[1][2]);
            c[1][0] = ffma2(m1, q1.y, c[1][0]);
            c[1][1] = ffma2(m1, q2.x, c[1][1]);
            c[1][2] = ffma2(m1, q2.y, c[1][2]);
        }
        #pragma unroll
        for (int rr = 0; rr < 2; ++rr) {
            float2 us = un2(sm2[rr]), uq = un2(sq2[rr]);
            float mu   = (us.x + us.y) * (1.0f / 24.0f);
            float var  = fmaf(-mu, mu, (uq.x + uq.y) * (1.0f / 24.0f));
            float rstd = rsqrtf(var + LN_EPS);
            ull mun = dup2(-mu), rsd = dup2(rstd);
            #pragma unroll
            for (int j = 0; j < 3; ++j)
                c[rr][j] = ffma2(rsd, ffma2(mun, S->cw.Bs2[q][3 + j], c[rr][j]),
                                 fadd2(S->cw.Bs2[q][j], s2[rr][j]));
        }
        #pragma unroll
        for (int j = 0; j < 3; ++j)
            *reinterpret_cast<ulonglong2*>(&S->sy[3 * q + j][r0]) =
                make_ulonglong2(c[0][j], c[1][j]);
        // stage next input
        S->sinb[nxt][2 * qa + 0][srow] = make_float2(nv.x, nv.y);
        S->sinb[nxt][2 * qa + 1][srow] = make_float2(nv.z, nv.w);
        __syncthreads();

        // ---- Phase D (layer2): ns2 = tanh(y@Wr2 + br2), own 3 pairs, 2 rows ----
        ull d[2][3];
        d[0][0] = d[1][0] = S->cw.Bs2[q][6];
        d[0][1] = d[1][1] = S->cw.Bs2[q][7];
        d[0][2] = d[1][2] = S->cw.Bs2[q][8];
        #pragma unroll
        for (int pp = 0; pp < 24; ++pp) {
            const ulonglong2* wq = reinterpret_cast<const ulonglong2*>(S->cw.Wr2o[q][pp]);
            ulonglong2 q0 = wq[0], q1 = wq[1], q2 = wq[2];
            ulonglong2 Y = *reinterpret_cast<const ulonglong2*>(&S->sy[pp][r0]);
            float2 u0 = un2(Y.x), u1 = un2(Y.y);
            ull k0 = dup2(u0.x), k1 = dup2(u0.y);
            d[0][0] = ffma2(k0, q0.x, d[0][0]);
            d[0][1] = ffma2(k0, q0.y, d[0][1]);
            d[0][2] = ffma2(k0, q1.x, d[0][2]);
            d[0][0] = ffma2(k1, q1.y, d[0][0]);
            d[0][1] = ffma2(k1, q2.x, d[0][1]);
            d[0][2] = ffma2(k1, q2.y, d[0][2]);
            ull m0 = dup2(u1.x), m1 = dup2(u1.y);
            d[1][0] = ffma2(m0, q0.x, d[1][0]);
            d[1][1] = ffma2(m0, q0.y, d[1][1]);
            d[1][2] = ffma2(m0, q1.x, d[1][2]);
            d[1][0] = ffma2(m1, q1.y, d[1][0]);
            d[1][1] = ffma2(m1, q2.x, d[1][1]);
            d[1][2] = ffma2(m1, q2.y, d[1][2]);
        }
        #pragma unroll
        for (int rr = 0; rr < 2; ++rr) {
            #pragma unroll
            for (int j = 0; j < 3; ++j) {
                float2 u = un2(d[rr][j]);
                s2[rr][j] = pk2(tanh_f(u.x), tanh_f(u.y));
            }
        }
        // no trailing barrier: next Phase-A writes sx only; sy rewrite in next
        // Phase C is gated by the two barriers in between.
    }

    // ---- epilogue: sigmoid(LN(s2; g2,be2) @ Wout + bout) ----
    __syncthreads();
    #pragma unroll
    for (int j = 0; j < 3; ++j)
        *reinterpret_cast<ulonglong2*>(&S->sy[3 * q + j][r0]) =
            make_ulonglong2(s2[0][j], s2[1][j]);
    __syncthreads();

    if (q < 2) {
        const int row = 32 * q + lane;
        ull zp[24];
        #pragma unroll
        for (int pp = 0; pp < 24; ++pp) zp[pp] = S->sy[pp][row];
        ull sm2 = zp[0], sq2 = fmul2(zp[0], zp[0]);
        #pragma unroll
        for (int pp = 1; pp < 24; ++pp) {
            sm2 = fadd2(sm2, zp[pp]);
            sq2 = ffma2(zp[pp], zp[pp], sq2);
        }
        float2 us = un2(sm2), uq = un2(sq2);
        float mu   = (us.x + us.y) * (1.0f / 48.0f);
        float var  = fmaf(-mu, mu, (uq.x + uq.y) * (1.0f / 48.0f));
        float rstd = rsqrtf(var + LN_EPS);
        ull mun = dup2(-mu), rsd = dup2(rstd);
        ull acc = 0;
        #pragma unroll
        for (int pp = 0; pp < 24; ++pp) {
            ull hpair = fmul2(fadd2(zp[pp], mun), rsd);
            hpair = ffma2(hpair, S->cw.G2f[pp], S->cw.Be2f[pp]);
            acc = ffma2(hpair, S->cw.Wof[pp], acc);
        }
        float2 ua = un2(acc);
        float z = ua.x + ua.y + S->cw.bout;
        out[rowbase + row] = __fdividef(1.0f, 1.0f + __expf(-z));
    }
}

extern "C" void kernel_launch(void* const* d_in, const int* in_sizes, int n_in,
                              void* d_out, int out_size)
{
    const float* seq  = (const float*)d_in[0];
    const float* W1   = (const float*)d_in[1];
    const float* b1   = (const float*)d_in[2];
    const float* Wr1  = (const float*)d_in[3];
    const float* br1  = (const float*)d_in[4];
    const float* g1   = (const float*)d_in[5];
    const float* be1  = (const float*)d_in[6];
    const float* W2   = (const float*)d_in[7];
    const float* b2   = (const float*)d_in[8];
    const float* Wr2  = (const float*)d_in[9];
    const float* br2  = (const float*)d_in[10];
    const float* g2   = (const float*)d_in[11];
    const float* be2  = (const float*)d_in[12];
    const float* Wout = (const float*)d_in[13];
    const float* bout = (const float*)d_in[14];

    prep_kernel<<<1, 256>>>(W1, b1, Wr1, br1, g1, be1,
                            W2, b2, Wr2, br2, g2, be2, Wout, bout);

    static int smem_configured = 0;
    if (!smem_configured) {
        cudaFuncSetAttribute(rnn_main, cudaFuncAttributeMaxDynamicSharedMemorySize,
                             (int)sizeof(Smem8));
        smem_configured = 1;
    }

    const int B = in_sizes[0] / (T * F);     // 8192
    rnn_main<<<B / 64, 256, sizeof(Smem8)>>>(seq, (float*)d_out);
}

// round 8
// speedup vs baseline: 1.2659x; 1.1232x over previous
#include <cuda_runtime.h>

typedef unsigned long long ull;

static constexpr int T  = 256;
static constexpr int F  = 16;
static constexpr int U1 = 24;
static constexpr int U2 = 48;
#define LN_EPS 1e-3f

// ---------------- packed f32x2 helpers ----------------
__device__ __forceinline__ ull pk2(float lo, float hi) {
    ull r; asm("mov.b64 %0, {%1, %2};" : "=l"(r) : "f"(lo), "f"(hi)); return r;
}
__device__ __forceinline__ ull dup2(float v) { return pk2(v, v); }
__device__ __forceinline__ float2 un2(ull p) {
    float2 r; asm("mov.b64 {%0, %1}, %2;" : "=f"(r.x), "=f"(r.y) : "l"(p)); return r;
}
__device__ __forceinline__ ull ffma2(ull a, ull b, ull c) {
    ull d; asm("fma.rn.f32x2 %0, %1, %2, %3;" : "=l"(d) : "l"(a), "l"(b), "l"(c)); return d;
}
__device__ __forceinline__ ull fadd2(ull a, ull b) {
    ull d; asm("add.rn.f32x2 %0, %1, %2;" : "=l"(d) : "l"(a), "l"(b)); return d;
}
__device__ __forceinline__ ull fmul2(ull a, ull b) {
    ull d; asm("mul.rn.f32x2 %0, %1, %2;" : "=l"(d) : "l"(a), "l"(b)); return d;
}

// branch-free accurate tanh: 1 - 2/(1+e^{2x})
__device__ __forceinline__ float tanh_f(float x) {
    float e = __expf(2.0f * x);
    return 1.0f - __fdividef(2.0f, 1.0f + e);
}

__device__ __forceinline__ ull mkp(float lo, float hi) {
    return ((ull)__float_as_uint(hi) << 32) | __float_as_uint(lo);
}

// split named barriers (ids 1,2; count = 2*128: each thread arrives once then syncs once)
#define BAR_ARRIVE1() asm volatile("bar.arrive 1, 256;" ::: "memory")
#define BAR_SYNC1()   asm volatile("bar.sync   1, 256;" ::: "memory")
#define BAR_ARRIVE2() asm volatile("bar.arrive 2, 256;" ::: "memory")
#define BAR_SYNC2()   asm volatile("bar.sync   2, 256;" ::: "memory")

// ---------------- fused weight bundle ----------------
// Phase1: ns1 = tanh(in@W1r + ns1_prev@Wr1 + b1r),  W1r = W1@Wr1
// Phase2: ns2 = tanh(rstd*(ns1@M) - rstd*mu*Cm + ns2_prev@Wr2 + b2n)
//   M = (g1.*W2)@Wr2, Cm = colsum(M), b2n = (b2 + be1@W2)@Wr2 + br2
// All k-pair-merged, per-warp unit slices (w: u1 pairs 3w+j, u2 pairs 6w+j).
struct __align__(16) CW2 {
    ull W1rm[4][8][6];    // [w][kp][j]: j0..2 k=2kp, j3..5 k=2kp+1
    ull Wr1m[4][12][6];
    ull Mm  [4][12][12];  // [w][p][j]: j0..5 k=2p, j6..11 k=2p+1
    ull Wr2m[4][24][12];
    ull B1r [4][3];
    ull B2n [4][6];
    ull Cmp [4][6];
    ull G2f [24];
    ull Be2f[24];
    ull Wof [24];
    float bout;
    float pad[3];
};
__device__ CW2 d_stage;

// ---------------- prep kernel ----------------
__global__ void prep_kernel(const float* __restrict__ W1,  const float* __restrict__ b1,
                            const float* __restrict__ Wr1, const float* __restrict__ br1,
                            const float* __restrict__ g1,  const float* __restrict__ be1,
                            const float* __restrict__ W2,  const float* __restrict__ b2,
                            const float* __restrict__ Wr2, const float* __restrict__ br2,
                            const float* __restrict__ g2,  const float* __restrict__ be2,
                            const float* __restrict__ Wout, const float* __restrict__ bout)
{
    const int tid = threadIdx.x;  // 256 threads

    // W1rm: W1r[k][u] = sum_v W1[k][v]*Wr1[v][u]
    for (int idx = tid; idx < 4 * 8 * 6; idx += 256) {
        int w = idx / 48, kp = (idx / 6) % 8, j = idx % 6;
        int k = 2 * kp + j / 3, u = 6 * w + 2 * (j % 3);
        float lo = 0.f, hi = 0.f;
        for (int v = 0; v < U1; ++v) {
            float a = W1[k * U1 + v];
            lo += a * Wr1[v * U1 + u];
            hi += a * Wr1[v * U1 + u + 1];
        }
        d_stage.W1rm[w][kp][j] = mkp(lo, hi);
    }
    // Wr1m (validated layout from R4)
    for (int idx = tid; idx < 4 * 12 * 6; idx += 256) {
        int w = idx / 72, p = (idx / 6) % 12, j = idx % 6;
        int k = 2 * p + j / 3, u = 6 * w + 2 * (j % 3);
        d_stage.Wr1m[w][p][j] = mkp(Wr1[k * U1 + u], Wr1[k * U1 + u + 1]);
    }
    // Mm: M[k][u] = sum_v g1[k]*W2[k][v]*Wr2[v][u]
    for (int idx = tid; idx < 4 * 12 * 12; idx += 256) {
        int w = idx / 144, p = (idx / 12) % 12, j = idx % 12;
        int k = 2 * p + j / 6, u = 12 * w + 2 * (j % 6);
        float lo = 0.f, hi = 0.f;
        for (int v = 0; v < U2; ++v) {
            float a = g1[k] * W2[k * U2 + v];
            lo += a * Wr2[v * U2 + u];
            hi += a * Wr2[v * U2 + u + 1];
        }
        d_stage.Mm[w][p][j] = mkp(lo, hi);
    }
    // Wr2m (validated layout from R4)
    for (int idx = tid; idx < 4 * 24 * 12; idx += 256) {
        int w = idx / 288, p = (idx % 288) / 12, j = idx % 12;
        int k = 2 * p + j / 6, u = 12 * w + 2 * (j % 6);
        d_stage.Wr2m[w][p][j] = mkp(Wr2[k * U2 + u], Wr2[k * U2 + u + 1]);
    }
    // B1r: b1r[u] = br1[u] + sum_k b1[k]*Wr1[k][u]
    for (int idx = tid; idx < 12; idx += 256) {
        int w = idx / 3, j = idx % 3, u = 6 * w + 2 * j;
        float lo = br1[u], hi = br1[u + 1];
        for (int k = 0; k < U1; ++k) {
            lo += b1[k] * Wr1[k * U1 + u];
            hi += b1[k] * Wr1[k * U1 + u + 1];
        }
        d_stage.B1r[w][j] = mkp(lo, hi);
    }
    // B2n: b2n[u] = br2[u] + sum_v (b2[v] + be1@W2[v]) * Wr2[v][u]
    // Cmp: Cm[u] = sum_v (sum_k g1[k]W2[k][v]) * Wr2[v][u]
    for (int idx = tid; idx < 24; idx += 256) {
        int w = idx / 6, j = idx % 6, u = 12 * w + 2 * j;
        float blo = br2[u], bhi = br2[u + 1];
        float clo = 0.f, chi = 0.f;
        for (int v = 0; v < U2; ++v) {
            float bf = b2[v], cv = 0.f;
            for (int k = 0; k < U1; ++k) {
                bf += be1[k] * W2[k * U2 + v];
                cv += g1[k] * W2[k * U2 + v];
            }
            blo += bf * Wr2[v * U2 + u];
            bhi += bf * Wr2[v * U2 + u + 1];
            clo += cv * Wr2[v * U2 + u];
            chi += cv * Wr2[v * U2 + u + 1];
        }
        d_stage.B2n[w][j] = mkp(blo, bhi);
        d_stage.Cmp[w][j] = mkp(clo, chi);
    }
    for (int idx = tid; idx < 24; idx += 256) {
        int u = 2 * idx;
        d_stage.G2f[idx]  = mkp(g2[u],   g2[u + 1]);
        d_stage.Be2f[idx] = mkp(be2[u],  be2[u + 1]);
        d_stage.Wof[idx]  = mkp(Wout[u], Wout[u + 1]);
    }
    if (tid == 0) d_stage.bout = bout[0];
}

// ---------------- smem layout ----------------
struct __align__(16) Smem2 {
    CW2 cw;
    ull sn[2][12][64];        // ns1 pairs [buf][pair][row]
    ull sy[2][24][64];        // ns2 pairs
    float sinb[2][16][66];    // staged input [buf][feat][row(padded)]
};

// ---------------- main scan kernel ----------------
// 128 threads = 4 warps; lane r -> rows 2r,2r+1; warp w -> unit slice.
// Two fused phases per step; 2 split barriers per step.
__global__ __launch_bounds__(128, 1)
void rnn_main(const float* __restrict__ seq, float* __restrict__ out)
{
    extern __shared__ __align__(16) char smem_raw[];
    Smem2* S = reinterpret_cast<Smem2*>(smem_raw);

    const int tid = threadIdx.x;
    const int w = tid >> 5;
    const int r = tid & 31;
    const int r0 = 2 * r;
    const int rowbase = blockIdx.x * 64;

    // cooperative weight copy
    {
        const ull* gsrc = reinterpret_cast<const ull*>(&d_stage);
        ull* sdst = reinterpret_cast<ull*>(&S->cw);
        const int N = (int)(sizeof(CW2) / 8);
        for (int i = tid; i < N; i += 128) sdst[i] = gsrc[i];
    }

    // input staging mapping (as R4): thread covers (row_l0, chunk), rows row_l0 and row_l0+32
    const int row_l0 = tid >> 2, ch = tid & 3;
    const float4* gp0 = reinterpret_cast<const float4*>(
                            seq + (size_t)(rowbase + row_l0) * (T * F)) + ch;
    const float4* gp1 = reinterpret_cast<const float4*>(
                            seq + (size_t)(rowbase + row_l0 + 32) * (T * F)) + ch;

    // prologue: stage inputs t=0 and t=1; zero state buffers sn[1], sy[1]
    {
        float4 f0 = gp0[0], f1 = gp1[0];
        S->sinb[0][4 * ch + 0][row_l0] = f0.x;
        S->sinb[0][4 * ch + 1][row_l0] = f0.y;
        S->sinb[0][4 * ch + 2][row_l0] = f0.z;
        S->sinb[0][4 * ch + 3][row_l0] = f0.w;
        S->sinb[0][4 * ch + 0][row_l0 + 32] = f1.x;
        S->sinb[0][4 * ch + 1][row_l0 + 32] = f1.y;
        S->sinb[0][4 * ch + 2][row_l0 + 32] = f1.z;
        S->sinb[0][4 * ch + 3][row_l0 + 32] = f1.w;
        float4 g0 = gp0[4], g1v = gp1[4];
        S->sinb[1][4 * ch + 0][row_l0] = g0.x;
        S->sinb[1][4 * ch + 1][row_l0] = g0.y;
        S->sinb[1][4 * ch + 2][row_l0] = g0.z;
        S->sinb[1][4 * ch + 3][row_l0] = g0.w;
        S->sinb[1][4 * ch + 0][row_l0 + 32] = g1v.x;
        S->sinb[1][4 * ch + 1][row_l0 + 32] = g1v.y;
        S->sinb[1][4 * ch + 2][row_l0 + 32] = g1v.z;
        S->sinb[1][4 * ch + 3][row_l0 + 32] = g1v.w;
    }
    {
        ull* z1 = &S->sn[1][0][0];
        for (int i = tid; i < 12 * 64; i += 128) z1[i] = 0ull;
        ull* z2 = &S->sy[1][0][0];
        for (int i = tid; i < 24 * 64; i += 128) z2[i] = 0ull;
    }
    __syncthreads();
    BAR_ARRIVE2();   // fake "phase-2 of step -1 done"

    for (int t = 0; t < T; ++t) {
        const int cur = t & 1, oth = cur ^ 1;
        const int tn2 = (t + 2 < T) ? (t + 2) : (T - 1);
        float4 nx0 = gp0[tn2 * 4];
        float4 nx1 = gp1[tn2 * 4];

        // ======== Phase 1: ns1 = tanh(in@W1r + ns1_prev@Wr1 + b1r) ========
        ull a00 = S->cw.B1r[w][0], a01 = S->cw.B1r[w][1], a02 = S->cw.B1r[w][2];
        ull a10 = a00, a11 = a01, a12 = a02;
        #pragma unroll
        for (int kp = 0; kp < 8; ++kp) {
            const ulonglong2* q = reinterpret_cast<const ulonglong2*>(S->cw.W1rm[w][kp]);
            ulonglong2 q0 = q[0], q1 = q[1], q2 = q[2];
            float2 f0 = *reinterpret_cast<const float2*>(&S->sinb[cur][2 * kp][r0]);
            float2 f1 = *reinterpret_cast<const float2*>(&S->sinb[cur][2 * kp + 1][r0]);
            ull k00 = dup2(f0.x), k01 = dup2(f0.y);
            ull k10 = dup2(f1.x), k11 = dup2(f1.y);
            a00 = ffma2(k00, q0.x, a00); a01 = ffma2(k00, q0.y, a01); a02 = ffma2(k00, q1.x, a02);
            a00 = ffma2(k10, q1.y, a00); a01 = ffma2(k10, q2.x, a01); a02 = ffma2(k10, q2.y, a02);
            a10 = ffma2(k01, q0.x, a10); a11 = ffma2(k01, q0.y, a11); a12 = ffma2(k01, q1.x, a12);
            a10 = ffma2(k11, q1.y, a10); a11 = ffma2(k11, q2.x, a11); a12 = ffma2(k11, q2.y, a12);
        }
        #pragma unroll
        for (int pp = 0; pp < 12; ++pp) {
            const ulonglong2* q = reinterpret_cast<const ulonglong2*>(S->cw.Wr1m[w][pp]);
            ulonglong2 q0 = q[0], q1 = q[1], q2 = q[2];
            ulonglong2 X = *reinterpret_cast<const ulonglong2*>(&S->sn[oth][pp][r0]);
            float2 u0 = un2(X.x), u1 = un2(X.y);
            ull k0 = dup2(u0.x), k1 = dup2(u0.y);
            a00 = ffma2(k0, q0.x, a00); a01 = ffma2(k0, q0.y, a01); a02 = ffma2(k0, q1.x, a02);
            a00 = ffma2(k1, q1.y, a00); a01 = ffma2(k1, q2.x, a01); a02 = ffma2(k1, q2.y, a02);
            ull m0 = dup2(u1.x), m1 = dup2(u1.y);
            a10 = ffma2(m0, q0.x, a10); a11 = ffma2(m0, q0.y, a11); a12 = ffma2(m0, q1.x, a12);
            a10 = ffma2(m1, q1.y, a10); a11 = ffma2(m1, q2.x, a11); a12 = ffma2(m1, q2.y, a12);
        }
        {
            float2 u0, u1;
            u0 = un2(a00); u1 = un2(a10);
            *reinterpret_cast<ulonglong2*>(&S->sn[cur][3 * w + 0][r0]) =
                make_ulonglong2(pk2(tanh_f(u0.x), tanh_f(u0.y)), pk2(tanh_f(u1.x), tanh_f(u1.y)));
            u0 = un2(a01); u1 = un2(a11);
            *reinterpret_cast<ulonglong2*>(&S->sn[cur][3 * w + 1][r0]) =
                make_ulonglong2(pk2(tanh_f(u0.x), tanh_f(u0.y)), pk2(tanh_f(u1.x), tanh_f(u1.y)));
            u0 = un2(a02); u1 = un2(a12);
            *reinterpret_cast<ulonglong2*>(&S->sn[cur][3 * w + 2][r0]) =
                make_ulonglong2(pk2(tanh_f(u0.x), tanh_f(u0.y)), pk2(tanh_f(u1.x), tanh_f(u1.y)));
        }
        BAR_ARRIVE1();    // sn[cur] slice published

        // ======== Phase 2a: state part  accs = b2n + ns2_prev@Wr2 ========
        BAR_SYNC2();      // all of previous step's phase-2 done (sy[oth] ready, WARs clear)
        ull e00 = S->cw.B2n[w][0], e01 = S->cw.B2n[w][1], e02 = S->cw.B2n[w][2];
        ull e03 = S->cw.B2n[w][3], e04 = S->cw.B2n[w][4], e05 = S->cw.B2n[w][5];
        ull e10 = e00, e11 = e01, e12 = e02, e13 = e03, e14 = e04, e15 = e05;
        #pragma unroll
        for (int pp = 0; pp < 24; ++pp) {
            const ulonglong2* q = reinterpret_cast<const ulonglong2*>(S->cw.Wr2m[w][pp]);
            ulonglong2 q0 = q[0], q1 = q[1], q2 = q[2];
            ulonglong2 q3 = q[3], q4 = q[4], q5 = q[5];
            ulonglong2 Y = *reinterpret_cast<const ulonglong2*>(&S->sy[oth][pp][r0]);
            float2 u0 = un2(Y.x), u1 = un2(Y.y);
            ull k0 = dup2(u0.x), k1 = dup2(u0.y);
            e00 = ffma2(k0, q0.x, e00); e01 = ffma2(k0, q0.y, e01); e02 = ffma2(k0, q1.x, e02);
            e03 = ffma2(k0, q1.y, e03); e04 = ffma2(k0, q2.x, e04); e05 = ffma2(k0, q2.y, e05);
            e00 = ffma2(k1, q3.x, e00); e01 = ffma2(k1, q3.y, e01); e02 = ffma2(k1, q4.x, e02);
            e03 = ffma2(k1, q4.y, e03); e04 = ffma2(k1, q5.x, e04); e05 = ffma2(k1, q5.y, e05);
            ull m0 = dup2(u1.x), m1 = dup2(u1.y);
            e10 = ffma2(m0, q0.x, e10); e11 = ffma2(m0, q0.y, e11); e12 = ffma2(m0, q1.x, e12);
            e13 = ffma2(m0, q1.y, e13); e14 = ffma2(m0, q2.x, e14); e15 = ffma2(m0, q2.y, e15);
            e10 = ffma2(m1, q3.x, e10); e11 = ffma2(m1, q3.y, e11); e12 = ffma2(m1, q4.x, e12);
            e13 = ffma2(m1, q4.y, e13); e14 = ffma2(m1, q5.x, e14); e15 = ffma2(m1, q5.y, e15);
        }

        // ======== Phase 2b: M part (needs sn[cur] from all warps) ========
        BAR_SYNC1();
        // stage input t+2 (all phase-1 reads of sinb[cur] are done)
        S->sinb[cur][4 * ch + 0][row_l0] = nx0.x;
        S->sinb[cur][4 * ch + 1][row_l0] = nx0.y;
        S->sinb[cur][4 * ch + 2][row_l0] = nx0.z;
        S->sinb[cur][4 * ch + 3][row_l0] = nx0.w;
        S->sinb[cur][4 * ch + 0][row_l0 + 32] = nx1.x;
        S->sinb[cur][4 * ch + 1][row_l0 + 32] = nx1.y;
        S->sinb[cur][4 * ch + 2][row_l0 + 32] = nx1.z;
        S->sinb[cur][4 * ch + 3][row_l0 + 32] = nx1.w;

        ull c00 = 0, c01 = 0, c02 = 0, c03 = 0, c04 = 0, c05 = 0;
        ull c10 = 0, c11 = 0, c12 = 0, c13 = 0, c14 = 0, c15 = 0;
        ull sm0 = 0, sm1 = 0, sq0 = 0, sq1 = 0;
        #pragma unroll
        for (int pp = 0; pp < 12; ++pp) {
            const ulonglong2* q = reinterpret_cast<const ulonglong2*>(S->cw.Mm[w][pp]);
            ulonglong2 q0 = q[0], q1 = q[1], q2 = q[2];
            ulonglong2 q3 = q[3], q4 = q[4], q5 = q[5];
            ulonglong2 X = *reinterpret_cast<const ulonglong2*>(&S->sn[cur][pp][r0]);
            sm0 = fadd2(sm0, X.x); sq0 = ffma2(X.x, X.x, sq0);
            sm1 = fadd2(sm1, X.y); sq1 = ffma2(X.y, X.y, sq1);
            float2 u0 = un2(X.x), u1 = un2(X.y);
            ull k0 = dup2(u0.x), k1 = dup2(u0.y);
            c00 = ffma2(k0, q0.x, c00); c01 = ffma2(k0, q0.y, c01); c02 = ffma2(k0, q1.x, c02);
            c03 = ffma2(k0, q1.y, c03); c04 = ffma2(k0, q2.x, c04); c05 = ffma2(k0, q2.y, c05);
            c00 = ffma2(k1, q3.x, c00); c01 = ffma2(k1, q3.y, c01); c02 = ffma2(k1, q4.x, c02);
            c03 = ffma2(k1, q4.y, c03); c04 = ffma2(k1, q5.x, c04); c05 = ffma2(k1, q5.y, c05);
            ull m0 = dup2(u1.x), m1 = dup2(u1.y);
            c10 = ffma2(m0, q0.x, c10); c11 = ffma2(m0, q0.y, c11); c12 = ffma2(m0, q1.x, c12);
            c13 = ffma2(m0, q1.y, c13); c14 = ffma2(m0, q2.x, c14); c15 = ffma2(m0, q2.y, c15);
            c10 = ffma2(m1, q3.x, c10); c11 = ffma2(m1, q3.y, c11); c12 = ffma2(m1, q4.x, c12);
            c13 = ffma2(m1, q4.y, c13); c14 = ffma2(m1, q5.x, c14); c15 = ffma2(m1, q5.y, c15);
        }
        // combine + tanh + publish ns2
        {
            float2 us = un2(sm0), uq = un2(sq0);
            float mu   = (us.x + us.y) * (1.0f / 24.0f);
            float var  = fmaf(-mu, mu, (uq.x + uq.y) * (1.0f / 24.0f));
            float rstd = rsqrtf(var + LN_EPS);
            ull mun = dup2(-mu), rsd = dup2(rstd);
            c00 = ffma2(rsd, ffma2(mun, S->cw.Cmp[w][0], c00), e00);
            c01 = ffma2(rsd, ffma2(mun, S->cw.Cmp[w][1], c01), e01);
            c02 = ffma2(rsd, ffma2(mun, S->cw.Cmp[w][2], c02), e02);
            c03 = ffma2(rsd, ffma2(mun, S->cw.Cmp[w][3], c03), e03);
            c04 = ffma2(rsd, ffma2(mun, S->cw.Cmp[w][4], c04), e04);
            c05 = ffma2(rsd, ffma2(mun, S->cw.Cmp[w][5], c05), e05);
            float2 vs = un2(sm1), vq = un2(sq1);
            float mu1   = (vs.x + vs.y) * (1.0f / 24.0f);
            float var1  = fmaf(-mu1, mu1, (vq.x + vq.y) * (1.0f / 24.0f));
            float rstd1 = rsqrtf(var1 + LN_EPS);
            ull mun1 = dup2(-mu1), rsd1 = dup2(rstd1);
            c10 = ffma2(rsd1, ffma2(mun1, S->cw.Cmp[w][0], c10), e10);
            c11 = ffma2(rsd1, ffma2(mun1, S->cw.Cmp[w][1], c11), e11);
            c12 = ffma2(rsd1, ffma2(mun1, S->cw.Cmp[w][2], c12), e12);
            c13 = ffma2(rsd1, ffma2(mun1, S->cw.Cmp[w][3], c13), e13);
            c14 = ffma2(rsd1, ffma2(mun1, S->cw.Cmp[w][4], c14), e14);
            c15 = ffma2(rsd1, ffma2(mun1, S->cw.Cmp[w][5], c15), e15);
        }
        {
            float2 u0, u1;
            u0 = un2(c00); u1 = un2(c10);
            *reinterpret_cast<ulonglong2*>(&S->sy[cur][6 * w + 0][r0]) =
                make_ulonglong2(pk2(tanh_f(u0.x), tanh_f(u0.y)), pk2(tanh_f(u1.x), tanh_f(u1.y)));
            u0 = un2(c01); u1 = un2(c11);
            *reinterpret_cast<ulonglong2*>(&S->sy[cur][6 * w + 1][r0]) =
                make_ulonglong2(pk2(tanh_f(u0.x), tanh_f(u0.y)), pk2(tanh_f(u1.x), tanh_f(u1.y)));
            u0 = un2(c02); u1 = un2(c12);
            *reinterpret_cast<ulonglong2*>(&S->sy[cur][6 * w + 2][r0]) =
                make_ulonglong2(pk2(tanh_f(u0.x), tanh_f(u0.y)), pk2(tanh_f(u1.x), tanh_f(u1.y)));
            u0 = un2(c03); u1 = un2(c13);
            *reinterpret_cast<ulonglong2*>(&S->sy[cur][6 * w + 3][r0]) =
                make_ulonglong2(pk2(tanh_f(u0.x), tanh_f(u0.y)), pk2(tanh_f(u1.x), tanh_f(u1.y)));
            u0 = un2(c04); u1 = un2(c14);
            *reinterpret_cast<ulonglong2*>(&S->sy[cur][6 * w + 4][r0]) =
                make_ulonglong2(pk2(tanh_f(u0.x), tanh_f(u0.y)), pk2(tanh_f(u1.x), tanh_f(u1.y)));
            u0 = un2(c05); u1 = un2(c15);
            *reinterpret_cast<ulonglong2*>(&S->sy[cur][6 * w + 5][r0]) =
                make_ulonglong2(pk2(tanh_f(u0.x), tanh_f(u0.y)), pk2(tanh_f(u1.x), tanh_f(u1.y)));
        }
        BAR_ARRIVE2();
    }

    BAR_SYNC2();   // final ns2 (in sy[1], since (T-1)&1 == 1) visible to all

    // ---- epilogue: sigmoid(LN(ns2; g2,be2) @ Wout + bout), rows 2r,2r+1 by warp 0 ----
    if (w == 0) {
        ull zp0[24], zp1[24];
        #pragma unroll
        for (int pp = 0; pp < 24; ++pp) {
            ulonglong2 X = *reinterpret_cast<const ulonglong2*>(&S->sy[1][pp][r0]);
            zp0[pp] = X.x; zp1[pp] = X.y;
        }
        float res[2];
        #pragma unroll
        for (int rr = 0; rr < 2; ++rr) {
            const ull* zp = rr ? zp1 : zp0;
            ull sm2 = zp[0], sq2 = fmul2(zp[0], zp[0]);
            #pragma unroll
            for (int pp = 1; pp < 24; ++pp) {
                sm2 = fadd2(sm2, zp[pp]);
                sq2 = ffma2(zp[pp], zp[pp], sq2);
            }
            float2 us = un2(sm2), uq = un2(sq2);
            float mu   = (us.x + us.y) * (1.0f / 48.0f);
            float var  = fmaf(-mu, mu, (uq.x + uq.y) * (1.0f / 48.0f));
            float rstd = rsqrtf(var + LN_EPS);
            ull mun = dup2(-mu), rsd = dup2(rstd);
            ull acc = 0;
            #pragma unroll
            for (int pp = 0; pp < 24; ++pp) {
                ull h = fmul2(fadd2(zp[pp], mun), rsd);
                h = ffma2(h, S->cw.G2f[pp], S->cw.Be2f[pp]);
                acc = ffma2(h, S->cw.Wof[pp], acc);
            }
            float2 ua = un2(acc);
            float z = ua.x + ua.y + S->cw.bout;
            res[rr] = __fdividef(1.0f, 1.0f + __expf(-z));
        }
        *reinterpret_cast<float2*>(&out[rowbase + r0]) = make_float2(res[0], res[1]);
    }
}

extern "C" void kernel_launch(void* const* d_in, const int* in_sizes, int n_in,
                              void* d_out, int out_size)
{
    const float* seq  = (const float*)d_in[0];
    const float* W1   = (const float*)d_in[1];
    const float* b1   = (const float*)d_in[2];
    const float* Wr1  = (const float*)d_in[3];
    const float* br1  = (const float*)d_in[4];
    const float* g1   = (const float*)d_in[5];
    const float* be1  = (const float*)d_in[6];
    const float* W2   = (const float*)d_in[7];
    const float* b2   = (const float*)d_in[8];
    const float* Wr2  = (const float*)d_in[9];
    const float* br2  = (const float*)d_in[10];
    const float* g2   = (const float*)d_in[11];
    const float* be2  = (const float*)d_in[12];
    const float* Wout = (const float*)d_in[13];
    const float* bout = (const float*)d_in[14];

    prep_kernel<<<1, 256>>>(W1, b1, Wr1, br1, g1, be1,
                            W2, b2, Wr2, br2, g2, be2, Wout, bout);

    static int smem_configured = 0;
    if (!smem_configured) {
        cudaFuncSetAttribute(rnn_main, cudaFuncAttributeMaxDynamicSharedMemorySize,
                             (int)sizeof(Smem2));
        smem_configured = 1;
    }

    const int B = in_sizes[0] / (T * F);     // 8192
    rnn_main<<<B / 64, 128, sizeof(Smem2)>>>(seq, (float*)d_out);
}

// round 11
// speedup vs baseline: 1.3246x; 1.0464x over previous
#include <cuda_runtime.h>

typedef unsigned long long ull;

static constexpr int T  = 256;
static constexpr int F  = 16;
static constexpr int U1 = 24;
static constexpr int U2 = 48;
#define LN_EPS 1e-3f

// ---------------- packed f32x2 helpers ----------------
__device__ __forceinline__ ull pk2(float lo, float hi) {
    ull r; asm("mov.b64 %0, {%1, %2};" : "=l"(r) : "f"(lo), "f"(hi)); return r;
}
__device__ __forceinline__ ull dup2(float v) { return pk2(v, v); }
__device__ __forceinline__ float2 un2(ull p) {
    float2 r; asm("mov.b64 {%0, %1}, %2;" : "=f"(r.x), "=f"(r.y) : "l"(p)); return r;
}
__device__ __forceinline__ ull ffma2(ull a, ull b, ull c) {
    ull d; asm("fma.rn.f32x2 %0, %1, %2, %3;" : "=l"(d) : "l"(a), "l"(b), "l"(c)); return d;
}
__device__ __forceinline__ ull fadd2(ull a, ull b) {
    ull d; asm("add.rn.f32x2 %0, %1, %2;" : "=l"(d) : "l"(a), "l"(b)); return d;
}
__device__ __forceinline__ ull fmul2(ull a, ull b) {
    ull d; asm("mul.rn.f32x2 %0, %1, %2;" : "=l"(d) : "l"(a), "l"(b)); return d;
}

// branch-free accurate tanh: 1 - 2/(1+e^{2x})
__device__ __forceinline__ float tanh_f(float x) {
    float e = __expf(2.0f * x);
    return 1.0f - __fdividef(2.0f, 1.0f + e);
}

__device__ __forceinline__ ull mkp(float lo, float hi) {
    return ((ull)__float_as_uint(hi) << 32) | __float_as_uint(lo);
}

// canonical one-sided pair barriers: one warp arrives (32), partner syncs (32), count 64
__device__ __forceinline__ void barw_arrive(int id) {
    asm volatile("bar.arrive %0, 64;" :: "r"(id) : "memory");
}
__device__ __forceinline__ void barw_sync(int id) {
    asm volatile("bar.sync %0, 64;" :: "r"(id) : "memory");
}

// ---------------- fused weight bundle (identical to validated R8) ----------------
struct __align__(16) CW2 {
    ull W1rm[4][8][6];    // W1@Wr1, [w][kp][j]
    ull Wr1m[4][12][6];
    ull Mm  [4][12][12];  // (g1.*W2)@Wr2
    ull Wr2m[4][24][12];
    ull B1r [4][3];
    ull B2n [4][6];
    ull Cmp [4][6];
    ull G2f [24];
    ull Be2f[24];
    ull Wof [24];
    float bout;
    float pad[3];
};
__device__ CW2 d_stage;

// ---------------- prep kernel (verbatim from validated R8) ----------------
__global__ void prep_kernel(const float* __restrict__ W1,  const float* __restrict__ b1,
                            const float* __restrict__ Wr1, const float* __restrict__ br1,
                            const float* __restrict__ g1,  const float* __restrict__ be1,
                            const float* __restrict__ W2,  const float* __restrict__ b2,
                            const float* __restrict__ Wr2, const float* __restrict__ br2,
                            const float* __restrict__ g2,  const float* __restrict__ be2,
                            const float* __restrict__ Wout, const float* __restrict__ bout)
{
    const int tid = threadIdx.x;  // 256 threads
    for (int idx = tid; idx < 4 * 8 * 6; idx += 256) {
        int w = idx / 48, kp = (idx / 6) % 8, j = idx % 6;
        int k = 2 * kp + j / 3, u = 6 * w + 2 * (j % 3);
        float lo = 0.f, hi = 0.f;
        for (int v = 0; v < U1; ++v) {
            float a = W1[k * U1 + v];
            lo += a * Wr1[v * U1 + u];
            hi += a * Wr1[v * U1 + u + 1];
        }
        d_stage.W1rm[w][kp][j] = mkp(lo, hi);
    }
    for (int idx = tid; idx < 4 * 12 * 6; idx += 256) {
        int w = idx / 72, p = (idx / 6) % 12, j = idx % 6;
        int k = 2 * p + j / 3, u = 6 * w + 2 * (j % 3);
        d_stage.Wr1m[w][p][j] = mkp(Wr1[k * U1 + u], Wr1[k * U1 + u + 1]);
    }
    for (int idx = tid; idx < 4 * 12 * 12; idx += 256) {
        int w = idx / 144, p = (idx / 12) % 12, j = idx % 12;
        int k = 2 * p + j / 6, u = 12 * w + 2 * (j % 6);
        float lo = 0.f, hi = 0.f;
        for (int v = 0; v < U2; ++v) {
            float a = g1[k] * W2[k * U2 + v];
            lo += a * Wr2[v * U2 + u];
            hi += a * Wr2[v * U2 + u + 1];
        }
        d_stage.Mm[w][p][j] = mkp(lo, hi);
    }
    for (int idx = tid; idx < 4 * 24 * 12; idx += 256) {
        int w = idx / 288, p = (idx % 288) / 12, j = idx % 12;
        int k = 2 * p + j / 6, u = 12 * w + 2 * (j % 6);
        d_stage.Wr2m[w][p][j] = mkp(Wr2[k * U2 + u], Wr2[k * U2 + u + 1]);
    }
    for (int idx = tid; idx < 12; idx += 256) {
        int w = idx / 3, j = idx % 3, u = 6 * w + 2 * j;
        float lo = br1[u], hi = br1[u + 1];
        for (int k = 0; k < U1; ++k) {
            lo += b1[k] * Wr1[k * U1 + u];
            hi += b1[k] * Wr1[k * U1 + u + 1];
        }
        d_stage.B1r[w][j] = mkp(lo, hi);
    }
    for (int idx = tid; idx < 24; idx += 256) {
        int w = idx / 6, j = idx % 6, u = 12 * w + 2 * j;
        float blo = br2[u], bhi = br2[u + 1];
        float clo = 0.f, chi = 0.f;
        for (int v = 0; v < U2; ++v) {
            float bf = b2[v], cv = 0.f;
            for (int k = 0; k < U1; ++k) {
                bf += be1[k] * W2[k * U2 + v];
                cv += g1[k] * W2[k * U2 + v];
            }
            blo += bf * Wr2[v * U2 + u];
            bhi += bf * Wr2[v * U2 + u + 1];
            clo += cv * Wr2[v * U2 + u];
            chi += cv * Wr2[v * U2 + u + 1];
        }
        d_stage.B2n[w][j] = mkp(blo, bhi);
        d_stage.Cmp[w][j] = mkp(clo, chi);
    }
    for (int idx = tid; idx < 24; idx += 256) {
        int u = 2 * idx;
        d_stage.G2f[idx]  = mkp(g2[u],   g2[u + 1]);
        d_stage.Be2f[idx] = mkp(be2[u],  be2[u + 1]);
        d_stage.Wof[idx]  = mkp(Wout[u], Wout[u + 1]);
    }
    if (tid == 0) d_stage.bout = bout[0];
}

// ---------------- smem layout ----------------
struct __align__(16) Smem3 {
    CW2 cw;
    ull sn[2][12][64];        // ns1 pairs [buf][pair][row]
    ull sy[2][24][64];        // ns2 pairs
    ull pb1[4][3][64];        // phase1 partials (A -> B)
    ull pb2[4][12][64];       // phase2 partials (B -> A): j0..5 = cB, j6..11 = eB
    float sinb[2][16][66];    // staged input
};

// ---------------- main scan kernel ----------------
// 256 threads = 8 warps = 4 pairs. Pair (w, w+4): slice w; kh=0 ("A") / kh=1 ("B")
// split each GEMM along k. lane r -> rows 2r, 2r+1. 64 rows/CTA, grid 128.
// Sync: 2 __syncthreads per step + 2 canonical one-sided pair barriers.
__global__ __launch_bounds__(256, 1)
void rnn_main(const float* __restrict__ seq, float* __restrict__ out)
{
    extern __shared__ __align__(16) char smem_raw[];
    Smem3* S = reinterpret_cast<Smem3*>(smem_raw);

    const int tid  = threadIdx.x;
    const int warp = tid >> 5;
    const int lane = tid & 31;
    const int w    = warp & 3;
    const int kh   = warp >> 2;       // 0 = A, 1 = B
    const int r0   = 2 * lane;
    const int rowbase = blockIdx.x * 64;
    const int pidA = 3 + w;           // A arrives, B syncs (phase 1 partial)
    const int pidB = 7 + w;           // B arrives, A syncs (phase 2 partial)

    // cooperative weight copy
    {
        const ull* gsrc = reinterpret_cast<const ull*>(&d_stage);
        ull* sdst = reinterpret_cast<ull*>(&S->cw);
        const int N = (int)(sizeof(CW2) / 8);
        for (int i = tid; i < N; i += 256) sdst[i] = gsrc[i];
    }

    // prologue: stage t=0,1 inputs; zero state buffers sn[1], sy[1]
    {
        const int prow = tid >> 2, pch = tid & 3;
        const float4* gq = reinterpret_cast<const float4*>(
                               seq + (size_t)(rowbase + prow) * (T * F)) + pch;
        float4 v0 = gq[0], v1 = gq[4];
        S->sinb[0][4 * pch + 0][prow] = v0.x;
        S->sinb[0][4 * pch + 1][prow] = v0.y;
        S->sinb[0][4 * pch + 2][prow] = v0.z;
        S->sinb[0][4 * pch + 3][prow] = v0.w;
        S->sinb[1][4 * pch + 0][prow] = v1.x;
        S->sinb[1][4 * pch + 1][prow] = v1.y;
        S->sinb[1][4 * pch + 2][prow] = v1.z;
        S->sinb[1][4 * pch + 3][prow] = v1.w;
        ull* z1 = &S->sn[1][0][0];
        for (int i = tid; i < 12 * 64; i += 256) z1[i] = 0ull;
        ull* z2 = &S->sy[1][0][0];
        for (int i = tid; i < 24 * 64; i += 256) z2[i] = 0ull;
    }
    __syncthreads();

    // per-step input staging (B warps only): 8 floats each
    const int srow = (tid & 127) >> 1, half = tid & 1;
    const float4* gpB = reinterpret_cast<const float4*>(
                            seq + (size_t)(rowbase + srow) * (T * F)) + half * 2;

    for (int t = 0; t < T; ++t) {
        const int cur = t & 1, oth = cur ^ 1;
        const int tn2 = (t + 2 < T) ? (t + 2) : (T - 1);
        float4 nv0, nv1;
        if (kh == 1) { nv0 = gpB[tn2 * 4]; nv1 = gpB[tn2 * 4 + 1]; }

        ull e00, e01, e02, e03, e04, e05, e10, e11, e12, e13, e14, e15;

        // ================= Phase 1 (k-split layer 1) + Phase 2a (e-halves) =====
        if (kh == 0) {
            // A: input part (W1rm) + Wr1 pp 0..1, ship partial, arrive
            ull a00 = S->cw.B1r[w][0], a01 = S->cw.B1r[w][1], a02 = S->cw.B1r[w][2];
            ull a10 = a00, a11 = a01, a12 = a02;
            #pragma unroll
            for (int kp = 0; kp < 8; ++kp) {
                const ulonglong2* q = reinterpret_cast<const ulonglong2*>(S->cw.W1rm[w][kp]);
                ulonglong2 q0 = q[0], q1 = q[1], q2 = q[2];
                float2 f0 = *reinterpret_cast<const float2*>(&S->sinb[cur][2 * kp][r0]);
                float2 f1 = *reinterpret_cast<const float2*>(&S->sinb[cur][2 * kp + 1][r0]);
                ull k00 = dup2(f0.x), k01 = dup2(f0.y);
                ull k10 = dup2(f1.x), k11 = dup2(f1.y);
                a00 = ffma2(k00, q0.x, a00); a01 = ffma2(k00, q0.y, a01); a02 = ffma2(k00, q1.x, a02);
                a00 = ffma2(k10, q1.y, a00); a01 = ffma2(k10, q2.x, a01); a02 = ffma2(k10, q2.y, a02);
                a10 = ffma2(k01, q0.x, a10); a11 = ffma2(k01, q0.y, a11); a12 = ffma2(k01, q1.x, a12);
                a10 = ffma2(k11, q1.y, a10); a11 = ffma2(k11, q2.x, a11); a12 = ffma2(k11, q2.y, a12);
            }
            #pragma unroll
            for (int pp = 0; pp < 2; ++pp) {
                const ulonglong2* q = reinterpret_cast<const ulonglong2*>(S->cw.Wr1m[w][pp]);
                ulonglong2 q0 = q[0], q1 = q[1], q2 = q[2];
                ulonglong2 X = *reinterpret_cast<const ulonglong2*>(&S->sn[oth][pp][r0]);
                float2 u0 = un2(X.x), u1 = un2(X.y);
                ull k0 = dup2(u0.x), k1 = dup2(u0.y);
                a00 = ffma2(k0, q0.x, a00); a01 = ffma2(k0, q0.y, a01); a02 = ffma2(k0, q1.x, a02);
                a00 = ffma2(k1, q1.y, a00); a01 = ffma2(k1, q2.x, a01); a02 = ffma2(k1, q2.y, a02);
                ull m0 = dup2(u1.x), m1 = dup2(u1.y);
                a10 = ffma2(m0, q0.x, a10); a11 = ffma2(m0, q0.y, a11); a12 = ffma2(m0, q1.x, a12);
                a10 = ffma2(m1, q1.y, a10); a11 = ffma2(m1, q2.x, a11); a12 = ffma2(m1, q2.y, a12);
            }
            *reinterpret_cast<ulonglong2*>(&S->pb1[w][0][r0]) = make_ulonglong2(a00, a10);
            *reinterpret_cast<ulonglong2*>(&S->pb1[w][1][r0]) = make_ulonglong2(a01, a11);
            *reinterpret_cast<ulonglong2*>(&S->pb1[w][2][r0]) = make_ulonglong2(a02, a12);
            barw_arrive(pidA);
            // Phase 2a (A's k-half of e): Wr2m pp 0..11, bias included
            e00 = S->cw.B2n[w][0]; e01 = S->cw.B2n[w][1]; e02 = S->cw.B2n[w][2];
            e03 = S->cw.B2n[w][3]; e04 = S->cw.B2n[w][4]; e05 = S->cw.B2n[w][5];
            e10 = e00; e11 = e01; e12 = e02; e13 = e03; e14 = e04; e15 = e05;
            #pragma unroll
            for (int pp = 0; pp < 12; ++pp) {
                const ulonglong2* q = reinterpret_cast<const ulonglong2*>(S->cw.Wr2m[w][pp]);
                ulonglong2 q0 = q[0], q1 = q[1], q2 = q[2];
                ulonglong2 q3 = q[3], q4 = q[4], q5 = q[5];
                ulonglong2 Y = *reinterpret_cast<const ulonglong2*>(&S->sy[oth][pp][r0]);
                float2 u0 = un2(Y.x), u1 = un2(Y.y);
                ull k0 = dup2(u0.x), k1 = dup2(u0.y);
                e00 = ffma2(k0, q0.x, e00); e01 = ffma2(k0, q0.y, e01); e02 = ffma2(k0, q1.x, e02);
                e03 = ffma2(k0, q1.y, e03); e04 = ffma2(k0, q2.x, e04); e05 = ffma2(k0, q2.y, e05);
                e00 = ffma2(k1, q3.x, e00); e01 = ffma2(k1, q3.y, e01); e02 = ffma2(k1, q4.x, e02);
                e03 = ffma2(k1, q4.y, e03); e04 = ffma2(k1, q5.x, e04); e05 = ffma2(k1, q5.y, e05);
                ull m0 = dup2(u1.x), m1 = dup2(u1.y);
                e10 = ffma2(m0, q0.x, e10); e11 = ffma2(m0, q0.y, e11); e12 = ffma2(m0, q1.x, e12);
                e13 = ffma2(m0, q1.y, e13); e14 = ffma2(m0, q2.x, e14); e15 = ffma2(m0, q2.y, e15);
                e10 = ffma2(m1, q3.x, e10); e11 = ffma2(m1, q3.y, e11); e12 = ffma2(m1, q4.x, e12);
                e13 = ffma2(m1, q4.y, e13); e14 = ffma2(m1, q5.x, e14); e15 = ffma2(m1, q5.y, e15);
            }
        } else {
            // B: Wr1 pp 2..11, sync for A's partial, combine, tanh, publish ns1
            ull a00 = 0, a01 = 0, a02 = 0, a10 = 0, a11 = 0, a12 = 0;
            #pragma unroll
            for (int pp = 2; pp < 12; ++pp) {
                const ulonglong2* q = reinterpret_cast<const ulonglong2*>(S->cw.Wr1m[w][pp]);
                ulonglong2 q0 = q[0], q1 = q[1], q2 = q[2];
                ulonglong2 X = *reinterpret_cast<const ulonglong2*>(&S->sn[oth][pp][r0]);
                float2 u0 = un2(X.x), u1 = un2(X.y);
                ull k0 = dup2(u0.x), k1 = dup2(u0.y);
                a00 = ffma2(k0, q0.x, a00); a01 = ffma2(k0, q0.y, a01); a02 = ffma2(k0, q1.x, a02);
                a00 = ffma2(k1, q1.y, a00); a01 = ffma2(k1, q2.x, a01); a02 = ffma2(k1, q2.y, a02);
                ull m0 = dup2(u1.x), m1 = dup2(u1.y);
                a10 = ffma2(m0, q0.x, a10); a11 = ffma2(m0, q0.y, a11); a12 = ffma2(m0, q1.x, a12);
                a10 = ffma2(m1, q1.y, a10); a11 = ffma2(m1, q2.x, a11); a12 = ffma2(m1, q2.y, a12);
            }
            barw_sync(pidA);
            {
                ulonglong2 P0 = *reinterpret_cast<const ulonglong2*>(&S->pb1[w][0][r0]);
                ulonglong2 P1 = *reinterpret_cast<const ulonglong2*>(&S->pb1[w][1][r0]);
                ulonglong2 P2 = *reinterpret_cast<const ulonglong2*>(&S->pb1[w][2][r0]);
                a00 = fadd2(a00, P0.x); a10 = fadd2(a10, P0.y);
                a01 = fadd2(a01, P1.x); a11 = fadd2(a11, P1.y);
                a02 = fadd2(a02, P2.x); a12 = fadd2(a12, P2.y);
            }
            {
                float2 u0, u1;
                u0 = un2(a00); u1 = un2(a10);
                *reinterpret_cast<ulonglong2*>(&S->sn[cur][3 * w + 0][r0]) =
                    make_ulonglong2(pk2(tanh_f(u0.x), tanh_f(u0.y)), pk2(tanh_f(u1.x), tanh_f(u1.y)));
                u0 = un2(a01); u1 = un2(a11);
                *reinterpret_cast<ulonglong2*>(&S->sn[cur][3 * w + 1][r0]) =
                    make_ulonglong2(pk2(tanh_f(u0.x), tanh_f(u0.y)), pk2(tanh_f(u1.x), tanh_f(u1.y)));
                u0 = un2(a02); u1 = un2(a12);
                *reinterpret_cast<ulonglong2*>(&S->sn[cur][3 * w + 2][r0]) =
                    make_ulonglong2(pk2(tanh_f(u0.x), tanh_f(u0.y)), pk2(tanh_f(u1.x), tanh_f(u1.y)));
            }
            // Phase 2a (B's k-half of e): Wr2m pp 12..23, zero bias
            e00 = e01 = e02 = e03 = e04 = e05 = 0ull;
            e10 = e11 = e12 = e13 = e14 = e15 = 0ull;
            #pragma unroll
            for (int pp = 12; pp < 24; ++pp) {
                const ulonglong2* q = reinterpret_cast<const ulonglong2*>(S->cw.Wr2m[w][pp]);
                ulonglong2 q0 = q[0], q1 = q[1], q2 = q[2];
                ulonglong2 q3 = q[3], q4 = q[4], q5 = q[5];
                ulonglong2 Y = *reinterpret_cast<const ulonglong2*>(&S->sy[oth][pp][r0]);
                float2 u0 = un2(Y.x), u1 = un2(Y.y);
                ull k0 = dup2(u0.x), k1 = dup2(u0.y);
                e00 = ffma2(k0, q0.x, e00); e01 = ffma2(k0, q0.y, e01); e02 = ffma2(k0, q1.x, e02);
                e03 = ffma2(k0, q1.y, e03); e04 = ffma2(k0, q2.x, e04); e05 = ffma2(k0, q2.y, e05);
                e00 = ffma2(k1, q3.x, e00); e01 = ffma2(k1, q3.y, e01); e02 = ffma2(k1, q4.x, e02);
                e03 = ffma2(k1, q4.y, e03); e04 = ffma2(k1, q5.x, e04); e05 = ffma2(k1, q5.y, e05);
                ull m0 = dup2(u1.x), m1 = dup2(u1.y);
                e10 = ffma2(m0, q0.x, e10); e11 = ffma2(m0, q0.y, e11); e12 = ffma2(m0, q1.x, e12);
                e13 = ffma2(m0, q1.y, e13); e14 = ffma2(m0, q2.x, e14); e15 = ffma2(m0, q2.y, e15);
                e10 = ffma2(m1, q3.x, e10); e11 = ffma2(m1, q3.y, e11); e12 = ffma2(m1, q4.x, e12);
                e13 = ffma2(m1, q4.y, e13); e14 = ffma2(m1, q5.x, e14); e15 = ffma2(m1, q5.y, e15);
            }
        }

        __syncthreads();   // sn[cur] visible to all; prev-step sy/pb WARs cleared

        // ================= Phase 2b: c = ns1@M (k-halves) + finalize ===========
        ull c00 = 0, c01 = 0, c02 = 0, c03 = 0, c04 = 0, c05 = 0;
        ull c10 = 0, c11 = 0, c12 = 0, c13 = 0, c14 = 0, c15 = 0;
        if (kh == 1) {
            #pragma unroll
            for (int pp = 6; pp < 12; ++pp) {
                const ulonglong2* q = reinterpret_cast<const ulonglong2*>(S->cw.Mm[w][pp]);
                ulonglong2 q0 = q[0], q1 = q[1], q2 = q[2];
                ulonglong2 q3 = q[3], q4 = q[4], q5 = q[5];
                ulonglong2 X = *reinterpret_cast<const ulonglong2*>(&S->sn[cur][pp][r0]);
                float2 u0 = un2(X.x), u1 = un2(X.y);
                ull k0 = dup2(u0.x), k1 = dup2(u0.y);
                c00 = ffma2(k0, q0.x, c00); c01 = ffma2(k0, q0.y, c01); c02 = ffma2(k0, q1.x, c02);
                c03 = ffma2(k0, q1.y, c03); c04 = ffma2(k0, q2.x, c04); c05 = ffma2(k0, q2.y, c05);
                c00 = ffma2(k1, q3.x, c00); c01 = ffma2(k1, q3.y, c01); c02 = ffma2(k1, q4.x, c02);
                c03 = ffma2(k1, q4.y, c03); c04 = ffma2(k1, q5.x, c04); c05 = ffma2(k1, q5.y, c05);
                ull m0 = dup2(u1.x), m1 = dup2(u1.y);
                c10 = ffma2(m0, q0.x, c10); c11 = ffma2(m0, q0.y, c11); c12 = ffma2(m0, q1.x, c12);
                c13 = ffma2(m0, q1.y, c13); c14 = ffma2(m0, q2.x, c14); c15 = ffma2(m0, q2.y, c15);
                c10 = ffma2(m1, q3.x, c10); c11 = ffma2(m1, q3.y, c11); c12 = ffma2(m1, q4.x, c12);
                c13 = ffma2(m1, q4.y, c13); c14 = ffma2(m1, q5.x, c14); c15 = ffma2(m1, q5.y, c15);
            }
            *reinterpret_cast<ulonglong2*>(&S->pb2[w][0][r0])  = make_ulonglong2(c00, c10);
            *reinterpret_cast<ulonglong2*>(&S->pb2[w][1][r0])  = make_ulonglong2(c01, c11);
            *reinterpret_cast<ulonglong2*>(&S->pb2[w][2][r0])  = make_ulonglong2(c02, c12);
            *reinterpret_cast<ulonglong2*>(&S->pb2[w][3][r0])  = make_ulonglong2(c03, c13);
            *reinterpret_cast<ulonglong2*>(&S->pb2[w][4][r0])  = make_ulonglong2(c04, c14);
            *reinterpret_cast<ulonglong2*>(&S->pb2[w][5][r0])  = make_ulonglong2(c05, c15);
            *reinterpret_cast<ulonglong2*>(&S->pb2[w][6][r0])  = make_ulonglong2(e00, e10);
            *reinterpret_cast<ulonglong2*>(&S->pb2[w][7][r0])  = make_ulonglong2(e01, e11);
            *reinterpret_cast<ulonglong2*>(&S->pb2[w][8][r0])  = make_ulonglong2(e02, e12);
            *reinterpret_cast<ulonglong2*>(&S->pb2[w][9][r0])  = make_ulonglong2(e03, e13);
            *reinterpret_cast<ulonglong2*>(&S->pb2[w][10][r0]) = make_ulonglong2(e04, e14);
            *reinterpret_cast<ulonglong2*>(&S->pb2[w][11][r0]) = make_ulonglong2(e05, e15);
            barw_arrive(pidB);
            // stage input t+2 (phase-1 reads of sinb[cur] all completed at syncthreads)
            S->sinb[cur][8 * half + 0][srow] = nv0.x;
            S->sinb[cur][8 * half + 1][srow] = nv0.y;
            S->sinb[cur][8 * half + 2][srow] = nv0.z;
            S->sinb[cur][8 * half + 3][srow] = nv0.w;
            S->sinb[cur][8 * half + 4][srow] = nv1.x;
            S->sinb[cur][8 * half + 5][srow] = nv1.y;
            S->sinb[cur][8 * half + 6][srow] = nv1.z;
            S->sinb[cur][8 * half + 7][srow] = nv1.w;
        } else {
            // A: Mm pp 0..5 + full LN stats (pp 0..11)
            ull sm0 = 0, sm1 = 0, sq0 = 0, sq1 = 0;
            #pragma unroll
            for (int pp = 0; pp < 12; ++pp) {
                ulonglong2 X = *reinterpret_cast<const ulonglong2*>(&S->sn[cur][pp][r0]);
                sm0 = fadd2(sm0, X.x); sq0 = ffma2(X.x, X.x, sq0);
                sm1 = fadd2(sm1, X.y); sq1 = ffma2(X.y, X.y, sq1);
                if (pp < 6) {
                    const ulonglong2* q = reinterpret_cast<const ulonglong2*>(S->cw.Mm[w][pp]);
                    ulonglong2 q0 = q[0], q1 = q[1], q2 = q[2];
                    ulonglong2 q3 = q[3], q4 = q[4], q5 = q[5];
                    float2 u0 = un2(X.x), u1 = un2(X.y);
                    ull k0 = dup2(u0.x), k1 = dup2(u0.y);
                    c00 = ffma2(k0, q0.x, c00); c01 = ffma2(k0, q0.y, c01); c02 = ffma2(k0, q1.x, c02);
                    c03 = ffma2(k0, q1.y, c03); c04 = ffma2(k0, q2.x, c04); c05 = ffma2(k0, q2.y, c05);
                    c00 = ffma2(k1, q3.x, c00); c01 = ffma2(k1, q3.y, c01); c02 = ffma2(k1, q4.x, c02);
                    c03 = ffma2(k1, q4.y, c03); c04 = ffma2(k1, q5.x, c04); c05 = ffma2(k1, q5.y, c05);
                    ull m0 = dup2(u1.x), m1 = dup2(u1.y);
                    c10 = ffma2(m0, q0.x, c10); c11 = ffma2(m0, q0.y, c11); c12 = ffma2(m0, q1.x, c12);
                    c13 = ffma2(m0, q1.y, c13); c14 = ffma2(m0, q2.x, c14); c15 = ffma2(m0, q2.y, c15);
                    c10 = ffma2(m1, q3.x, c10); c11 = ffma2(m1, q3.y, c11); c12 = ffma2(m1, q4.x, c12);
                    c13 = ffma2(m1, q4.y, c13); c14 = ffma2(m1, q5.x, c14); c15 = ffma2(m1, q5.y, c15);
                }
            }
            barw_sync(pidB);
            {
                ulonglong2 P;
                P = *reinterpret_cast<const ulonglong2*>(&S->pb2[w][0][r0]);  c00 = fadd2(c00, P.x); c10 = fadd2(c10, P.y);
                P = *reinterpret_cast<const ulonglong2*>(&S->pb2[w][1][r0]);  c01 = fadd2(c01, P.x); c11 = fadd2(c11, P.y);
                P = *reinterpret_cast<const ulonglong2*>(&S->pb2[w][2][r0]);  c02 = fadd2(c02, P.x); c12 = fadd2(c12, P.y);
                P = *reinterpret_cast<const ulonglong2*>(&S->pb2[w][3][r0]);  c03 = fadd2(c03, P.x); c13 = fadd2(c13, P.y);
                P = *reinterpret_cast<const ulonglong2*>(&S->pb2[w][4][r0]);  c04 = fadd2(c04, P.x); c14 = fadd2(c14, P.y);
                P = *reinterpret_cast<const ulonglong2*>(&S->pb2[w][5][r0]);  c05 = fadd2(c05, P.x); c15 = fadd2(c15, P.y);
                P = *reinterpret_cast<const ulonglong2*>(&S->pb2[w][6][r0]);  e00 = fadd2(e00, P.x); e10 = fadd2(e10, P.y);
                P = *reinterpret_cast<const ulonglong2*>(&S->pb2[w][7][r0]);  e01 = fadd2(e01, P.x); e11 = fadd2(e11, P.y);
                P = *reinterpret_cast<const ulonglong2*>(&S->pb2[w][8][r0]);  e02 = fadd2(e02, P.x); e12 = fadd2(e12, P.y);
                P = *reinterpret_cast<const ulonglong2*>(&S->pb2[w][9][r0]);  e03 = fadd2(e03, P.x); e13 = fadd2(e13, P.y);
                P = *reinterpret_cast<const ulonglong2*>(&S->pb2[w][10][r0]); e04 = fadd2(e04, P.x); e14 = fadd2(e14, P.y);
                P = *reinterpret_cast<const ulonglong2*>(&S->pb2[w][11][r0]); e05 = fadd2(e05, P.x); e15 = fadd2(e15, P.y);
            }
            {
                float2 us = un2(sm0), uq = un2(sq0);
                float mu   = (us.x + us.y) * (1.0f / 24.0f);
                float var  = fmaf(-mu, mu, (uq.x + uq.y) * (1.0f / 24.0f));
                float rstd = rsqrtf(var + LN_EPS);
                ull mun = dup2(-mu), rsd = dup2(rstd);
                c00 = ffma2(rsd, ffma2(mun, S->cw.Cmp[w][0], c00), e00);
                c01 = ffma2(rsd, ffma2(mun, S->cw.Cmp[w][1], c01), e01);
                c02 = ffma2(rsd, ffma2(mun, S->cw.Cmp[w][2], c02), e02);
                c03 = ffma2(rsd, ffma2(mun, S->cw.Cmp[w][3], c03), e03);
                c04 = ffma2(rsd, ffma2(mun, S->cw.Cmp[w][4], c04), e04);
                c05 = ffma2(rsd, ffma2(mun, S->cw.Cmp[w][5], c05), e05);
                float2 vs = un2(sm1), vq = un2(sq1);
                float mu1   = (vs.x + vs.y) * (1.0f / 24.0f);
                float var1  = fmaf(-mu1, mu1, (vq.x + vq.y) * (1.0f / 24.0f));
                float rstd1 = rsqrtf(var1 + LN_EPS);
                ull mun1 = dup2(-mu1), rsd1 = dup2(rstd1);
                c10 = ffma2(rsd1, ffma2(mun1, S->cw.Cmp[w][0], c10), e10);
                c11 = ffma2(rsd1, ffma2(mun1, S->cw.Cmp[w][1], c11), e11);
                c12 = ffma2(rsd1, ffma2(mun1, S->cw.Cmp[w][2], c12), e12);
                c13 = ffma2(rsd1, ffma2(mun1, S->cw.Cmp[w][3], c13), e13);
                c14 = ffma2(rsd1, ffma2(mun1, S->cw.Cmp[w][4], c14), e14);
                c15 = ffma2(rsd1, ffma2(mun1, S->cw.Cmp[w][5], c15), e15);
            }
            {
                float2 u0, u1;
                u0 = un2(c00); u1 = un2(c10);
                *reinterpret_cast<ulonglong2*>(&S->sy[cur][6 * w + 0][r0]) =
                    make_ulonglong2(pk2(tanh_f(u0.x), tanh_f(u0.y)), pk2(tanh_f(u1.x), tanh_f(u1.y)));
                u0 = un2(c01); u1 = un2(c11);
                *reinterpret_cast<ulonglong2*>(&S->sy[cur][6 * w + 1][r0]) =
                    make_ulonglong2(pk2(tanh_f(u0.x), tanh_f(u0.y)), pk2(tanh_f(u1.x), tanh_f(u1.y)));
                u0 = un2(c02); u1 = un2(c12);
                *reinterpret_cast<ulonglong2*>(&S->sy[cur][6 * w + 2][r0]) =
                    make_ulonglong2(pk2(tanh_f(u0.x), tanh_f(u0.y)), pk2(tanh_f(u1.x), tanh_f(u1.y)));
                u0 = un2(c03); u1 = un2(c13);
                *reinterpret_cast<ulonglong2*>(&S->sy[cur][6 * w + 3][r0]) =
                    make_ulonglong2(pk2(tanh_f(u0.x), tanh_f(u0.y)), pk2(tanh_f(u1.x), tanh_f(u1.y)));
                u0 = un2(c04); u1 = un2(c14);
                *reinterpret_cast<ulonglong2*>(&S->sy[cur][6 * w + 4][r0]) =
                    make_ulonglong2(pk2(tanh_f(u0.x), tanh_f(u0.y)), pk2(tanh_f(u1.x), tanh_f(u1.y)));
                u0 = un2(c05); u1 = un2(c15);
                *reinterpret_cast<ulonglong2*>(&S->sy[cur][6 * w + 5][r0]) =
                    make_ulonglong2(pk2(tanh_f(u0.x), tanh_f(u0.y)), pk2(tanh_f(u1.x), tanh_f(u1.y)));
            }
        }
        __syncthreads();   // sy[cur] + staged input visible; pb WARs cleared
    }

    // ---- epilogue: sigmoid(LN(ns2; g2,be2) @ Wout + bout) by warp 0 ----
    if (warp == 0) {
        ull zp0[24], zp1[24];
        #pragma unroll
        for (int pp = 0; pp < 24; ++pp) {
            ulonglong2 X = *reinterpret_cast<const ulonglong2*>(&S->sy[1][pp][r0]);
            zp0[pp] = X.x; zp1[pp] = X.y;
        }
        float res[2];
        #pragma unroll
        for (int rr = 0; rr < 2; ++rr) {
            const ull* zp = rr ? zp1 : zp0;
            ull sm2 = zp[0], sq2 = fmul2(zp[0], zp[0]);
            #pragma unroll
            for (int pp = 1; pp < 24; ++pp) {
                sm2 = fadd2(sm2, zp[pp]);
                sq2 = ffma2(zp[pp], zp[pp], sq2);
            }
            float2 us = un2(sm2), uq = un2(sq2);
            float mu   = (us.x + us.y) * (1.0f / 48.0f);
            float var  = fmaf(-mu, mu, (uq.x + uq.y) * (1.0f / 48.0f));
            float rstd = rsqrtf(var + LN_EPS);
            ull mun = dup2(-mu), rsd = dup2(rstd);
            ull acc = 0;
            #pragma unroll
            for (int pp = 0; pp < 24; ++pp) {
                ull h = fmul2(fadd2(zp[pp], mun), rsd);
                h = ffma2(h, S->cw.G2f[pp], S->cw.Be2f[pp]);
                acc = ffma2(h, S->cw.Wof[pp], acc);
            }
            float2 ua = un2(acc);
            float z = ua.x + ua.y + S->cw.bout;
            res[rr] = __fdividef(1.0f, 1.0f + __expf(-z));
        }
        *reinterpret_cast<float2*>(&out[rowbase + r0]) = make_float2(res[0], res[1]);
    }
}

extern "C" void kernel_launch(void* const* d_in, const int* in_sizes, int n_in,
                              void* d_out, int out_size)
{
    const float* seq  = (const float*)d_in[0];
    const float* W1   = (const float*)d_in[1];
    const float* b1   = (const float*)d_in[2];
    const float* Wr1  = (const float*)d_in[3];
    const float* br1  = (const float*)d_in[4];
    const float* g1   = (const float*)d_in[5];
    const float* be1  = (const float*)d_in[6];
    const float* W2   = (const float*)d_in[7];
    const float* b2   = (const float*)d_in[8];
    const float* Wr2  = (const float*)d_in[9];
    const float* br2  = (const float*)d_in[10];
    const float* g2   = (const float*)d_in[11];
    const float* be2  = (const float*)d_in[12];
    const float* Wout = (const float*)d_in[13];
    const float* bout = (const float*)d_in[14];

    prep_kernel<<<1, 256>>>(W1, b1, Wr1, br1, g1, be1,
                            W2, b2, Wr2, br2, g2, be2, Wout, bout);

    static int smem_configured = 0;
    if (!smem_configured) {
        cudaFuncSetAttribute(rnn_main, cudaFuncAttributeMaxDynamicSharedMemorySize,
                             (int)sizeof(Smem3));
        smem_configured = 1;
    }

    const int B = in_sizes[0] / (T * F);     // 8192
    rnn_main<<<B / 64, 256, sizeof(Smem3)>>>(seq, (float*)d_out);
}